// round 15
// baseline (speedup 1.0000x reference)
#include <cuda_runtime.h>
#include <cuda_bf16.h>
#include <stdint.h>
#include <math.h>

#define BB  2
#define CIN 512
#define CC  256
#define HH  48
#define WW  48
#define HWW 2304
#define LL  2304
#define DI  512
#define BL  (BB*LL)
#define BNF 0.9999950000374997f

typedef __nv_bfloat16 bf16;

// ------------------------- static scratch (no allocs) -------------------------
__device__ __align__(256) float g_xred[BL*CC];        // token-major
__device__ __align__(256) float g_p[BL*CC];
__device__ __align__(256) float g_featloc[BL*CC];
__device__ __align__(256) float g_featglob[BL*CC];
__device__ __align__(256) float g_xz[BL*2*DI];
__device__ __align__(256) float g_xm[4*BL*DI];
__device__ __align__(256) float g_projm[4*BL*48];
__device__ __align__(256) float g_dtb[4*BL*DI];
__device__ __align__(256) bf16  g_y[4*BL*DI];
// bf16 split activations
__device__ __align__(256) bf16 g_xthi[BL*CIN],  g_xtlo[BL*CIN];
__device__ __align__(256) bf16 g_xrhi[BL*CC],   g_xrlo[BL*CC];
__device__ __align__(256) bf16 g_xnhi[BL*CC],   g_xnlo[BL*CC];
__device__ __align__(256) bf16 g_hvhi[BL*CC],   g_hvlo[BL*CC];
__device__ __align__(256) bf16 g_yshi[BL*DI],   g_yslo[BL*DI];
// bf16 split weights
__device__ __align__(256) bf16 g_rwhi[CC*CIN],  g_rwlo[CC*CIN];
__device__ __align__(256) bf16 g_pwhi[CC*CC],   g_pwlo[CC*CC];
__device__ __align__(256) bf16 g_fwhi[CC*CC],   g_fwlo[CC*CC];
__device__ __align__(256) bf16 g_iwhi[2*DI*CC], g_iwlo[2*DI*CC];
__device__ __align__(256) bf16 g_owhi[CC*DI],   g_owlo[CC*DI];
// misc
__device__ __align__(256) float g_dtwT[16*DI];
__device__ __align__(256) float g_xpw[48*DI];
__device__ __align__(256) int   g_map[4*LL];
__device__ __align__(256) float g_msum[BB*36*CC];
__device__ __align__(256) float g_sv[BB*CC];
__device__ __align__(256) float g_wv[BB*2*CC];

__device__ __forceinline__ int seq_map(int dir, int t) {
    if (dir == 0) return t;
    if (dir == 1) return LL - 1 - t;
    int u = (dir == 2) ? t : (LL - 1 - t);
    int h = u % HH, w = u / HH;
    return h * WW + w;
}
__device__ __forceinline__ float silu_f(float x) { return x / (1.f + __expf(-x)); }
__device__ __forceinline__ void split_bf(float v, bf16& h, bf16& l) {
    h = __float2bfloat16(v);
    l = __float2bfloat16(v - __bfloat162float(h));
}

// ------------------ one-time prep ---------------------------------------------
__global__ void init_misc_k(const float* __restrict__ dtw, const float* __restrict__ xpw,
                            const float* __restrict__ rw, const float* __restrict__ pw,
                            const float* __restrict__ fw, const float* __restrict__ iw,
                            const float* __restrict__ ow)
{
    int i = blockIdx.x * 256 + threadIdx.x;
    if (i < 16 * DI) {
        int dd = i >> 4, r = i & 15;
        g_dtwT[r * DI + dd] = dtw[i];
    }
    if (i < 4 * LL) g_map[i] = seq_map(i / LL, i % LL);
    if (i < 48 * DI) {
        int j = i >> 9, k = i & 511;
        int src = (j < 16) ? j
                : (((j - 16) & 1) ? 32 + ((j - 16) >> 1) : 16 + ((j - 16) >> 1));
        g_xpw[i] = xpw[src * DI + k];
    }
    int o = i;
    if (o < CC*CIN) { split_bf(rw[o], g_rwhi[o], g_rwlo[o]); return; }
    o -= CC*CIN;
    if (o < CC*CC)  { split_bf(pw[o], g_pwhi[o], g_pwlo[o]); return; }
    o -= CC*CC;
    if (o < CC*CC)  { split_bf(fw[o], g_fwhi[o], g_fwlo[o]); return; }
    o -= CC*CC;
    if (o < 2*DI*CC){ split_bf(iw[o], g_iwhi[o], g_iwlo[o]); return; }
    o -= 2*DI*CC;
    if (o < CC*DI)  { split_bf(ow[o], g_owhi[o], g_owlo[o]); return; }
}

// ---------- input transpose: x[b][cin][hw] -> xT hi/lo ------------------------
__global__ void trans_in_k(const float* __restrict__ x)
{
    __shared__ float tile[32][33];
    int b = blockIdx.z;
    int l0 = blockIdx.x * 32, c0 = blockIdx.y * 32;
    int tx = threadIdx.x, ty = threadIdx.y;      // (32,8)
#pragma unroll
    for (int i = 0; i < 4; i++)
        tile[ty + i*8][tx] = x[((long long)b*CIN + c0 + ty + i*8) * HWW + l0 + tx];
    __syncthreads();
#pragma unroll
    for (int i = 0; i < 4; i++) {
        long long o = ((long long)b*HWW + l0 + ty + i*8) * CIN + c0 + tx;
        bf16 h, l;
        split_bf(tile[tx][ty + i*8], h, l);
        g_xthi[o] = h; g_xtlo[o] = l;
    }
}

// ======================= mma primitive ========================================
#define ASTR 40
__device__ __forceinline__ void mma16816(float* d, uint32_t a0, uint32_t a1,
                                         uint32_t a2, uint32_t a3,
                                         uint32_t b0, uint32_t b1)
{
    asm volatile(
        "mma.sync.aligned.m16n8k16.row.col.f32.bf16.bf16.f32 "
        "{%0,%1,%2,%3}, {%4,%5,%6,%7}, {%8,%9}, {%0,%1,%2,%3};\n"
        : "+f"(d[0]), "+f"(d[1]), "+f"(d[2]), "+f"(d[3])
        : "r"(a0), "r"(a1), "r"(a2), "r"(a3), "r"(b0), "r"(b1));
}

// ---------------- big 128x128 tensor GEMM (in_proj) ---------------------------
__global__ void __launch_bounds__(256) gemm_inproj_t3()
{
    __shared__ bf16 As[128 * ASTR];
    __shared__ bf16 Bs[128 * ASTR];
    const int K = CC;
    const int N = 2 * DI;
    int tid = threadIdx.x;
    int warp = tid >> 5, lane = tid & 31;
    int gID = lane >> 2, tig = lane & 3;
    int wm = (warp >> 2) * 64, wn = (warp & 3) * 32;
    int m0 = blockIdx.y * 128, n0 = blockIdx.x * 128;

    int u0 = tid, u1 = tid + 256;
    int ar0 = u0 >> 2, ac0 = (u0 & 3) * 8;
    int ar1 = u1 >> 2, ac1 = (u1 & 3) * 8;

    uint4 ra[2], rb[2];
    ra[0] = *(const uint4*)(g_xnhi + (long long)(m0 + ar0) * K + ac0);
    ra[1] = *(const uint4*)(g_xnhi + (long long)(m0 + ar1) * K + ac1);
    rb[0] = *(const uint4*)(g_iwhi + (long long)(n0 + ar0) * K + ac0);
    rb[1] = *(const uint4*)(g_iwhi + (long long)(n0 + ar1) * K + ac1);

    float acc[4][4][4] = {};
    const int G = 24;

    for (int g = 0; g < G; g++) {
        *(uint4*)&As[ar0 * ASTR + ac0] = ra[0];
        *(uint4*)&As[ar1 * ASTR + ac1] = ra[1];
        *(uint4*)&Bs[ar0 * ASTR + ac0] = rb[0];
        *(uint4*)&Bs[ar1 * ASTR + ac1] = rb[1];
        __syncthreads();
        int gn = g + 1;
        if (gn < G) {
            int pass = gn >> 3;
            int kk = (gn & 7) * 32;
            const bf16* Ag = (pass == 1) ? g_xnlo : g_xnhi;
            const bf16* Bg = (pass == 2) ? g_iwlo : g_iwhi;
            ra[0] = *(const uint4*)(Ag + (long long)(m0 + ar0) * K + kk + ac0);
            ra[1] = *(const uint4*)(Ag + (long long)(m0 + ar1) * K + kk + ac1);
            rb[0] = *(const uint4*)(Bg + (long long)(n0 + ar0) * K + kk + ac0);
            rb[1] = *(const uint4*)(Bg + (long long)(n0 + ar1) * K + kk + ac1);
        }
#pragma unroll
        for (int ks = 0; ks < 32; ks += 16) {
            uint32_t af[4][4], bfr[4][2];
#pragma unroll
            for (int mi = 0; mi < 4; mi++) {
                int r = wm + mi*16 + gID;
                af[mi][0] = *(const uint32_t*)&As[r * ASTR + ks + 2*tig];
                af[mi][1] = *(const uint32_t*)&As[(r+8) * ASTR + ks + 2*tig];
                af[mi][2] = *(const uint32_t*)&As[r * ASTR + ks + 2*tig + 8];
                af[mi][3] = *(const uint32_t*)&As[(r+8) * ASTR + ks + 2*tig + 8];
            }
#pragma unroll
            for (int nj = 0; nj < 4; nj++) {
                int r = wn + nj*8 + gID;
                bfr[nj][0] = *(const uint32_t*)&Bs[r * ASTR + ks + 2*tig];
                bfr[nj][1] = *(const uint32_t*)&Bs[r * ASTR + ks + 2*tig + 8];
            }
#pragma unroll
            for (int mi = 0; mi < 4; mi++)
#pragma unroll
                for (int nj = 0; nj < 4; nj++)
                    mma16816(acc[mi][nj], af[mi][0], af[mi][1], af[mi][2], af[mi][3],
                             bfr[nj][0], bfr[nj][1]);
        }
        __syncthreads();
    }

#pragma unroll
    for (int mi = 0; mi < 4; mi++)
#pragma unroll
    for (int nj = 0; nj < 4; nj++) {
        int m = m0 + wm + mi*16 + gID;
        int n = n0 + wn + nj*8 + 2*tig;
        float* a = acc[mi][nj];
#pragma unroll
        for (int half = 0; half < 2; half++) {
            int mm = m + half * 8;
            *(float2*)&g_xz[(long long)mm * N + n] = make_float2(a[half*2], a[half*2+1]);
        }
    }
}

// ---------------- small 64x64 tensor GEMM (4 warps, warp 32x32) ---------------
template<int MODE>
__global__ void __launch_bounds__(128) gemm_t3s(
    const bf16* __restrict__ Ahi, const bf16* __restrict__ Alo,
    const bf16* __restrict__ Bhi, const bf16* __restrict__ Blo,
    float* __restrict__ outf, bf16* __restrict__ ohi, bf16* __restrict__ olo,
    int N, int K,
    const float* __restrict__ sc, const float* __restrict__ bi,
    const float* __restrict__ extra)
{
    __shared__ bf16 As[64 * ASTR];
    __shared__ bf16 Bs[64 * ASTR];
    int tid = threadIdx.x;
    int warp = tid >> 5, lane = tid & 31;
    int gID = lane >> 2, tig = lane & 3;
    int wm = (warp >> 1) * 32, wn = (warp & 1) * 32;
    int m0 = blockIdx.y * 64, n0 = blockIdx.x * 64;

    int ar = tid >> 2;
    int ac = (tid & 3) * 8;

    int K32 = K >> 5;
    int G = 3 * K32;

    uint4 ra[2], rb[2];
    ra[0] = *(const uint4*)(Ahi + (long long)(m0 + ar) * K + ac);
    ra[1] = *(const uint4*)(Ahi + (long long)(m0 + ar + 32) * K + ac);
    rb[0] = *(const uint4*)(Bhi + (long long)(n0 + ar) * K + ac);
    rb[1] = *(const uint4*)(Bhi + (long long)(n0 + ar + 32) * K + ac);

    float acc[2][4][4] = {};

    for (int g = 0; g < G; g++) {
        *(uint4*)&As[ar * ASTR + ac] = ra[0];
        *(uint4*)&As[(ar + 32) * ASTR + ac] = ra[1];
        *(uint4*)&Bs[ar * ASTR + ac] = rb[0];
        *(uint4*)&Bs[(ar + 32) * ASTR + ac] = rb[1];
        __syncthreads();
        int gn = g + 1;
        if (gn < G) {
            int pass = gn / K32;
            int kk = (gn - pass * K32) * 32;
            const bf16* Ag = (pass == 1) ? Alo : Ahi;
            const bf16* Bg = (pass == 2) ? Blo : Bhi;
            ra[0] = *(const uint4*)(Ag + (long long)(m0 + ar) * K + kk + ac);
            ra[1] = *(const uint4*)(Ag + (long long)(m0 + ar + 32) * K + kk + ac);
            rb[0] = *(const uint4*)(Bg + (long long)(n0 + ar) * K + kk + ac);
            rb[1] = *(const uint4*)(Bg + (long long)(n0 + ar + 32) * K + kk + ac);
        }
#pragma unroll
        for (int ks = 0; ks < 32; ks += 16) {
            uint32_t af[2][4], bfr[4][2];
#pragma unroll
            for (int mi = 0; mi < 2; mi++) {
                int r = wm + mi*16 + gID;
                af[mi][0] = *(const uint32_t*)&As[r * ASTR + ks + 2*tig];
                af[mi][1] = *(const uint32_t*)&As[(r+8) * ASTR + ks + 2*tig];
                af[mi][2] = *(const uint32_t*)&As[r * ASTR + ks + 2*tig + 8];
                af[mi][3] = *(const uint32_t*)&As[(r+8) * ASTR + ks + 2*tig + 8];
            }
#pragma unroll
            for (int nj = 0; nj < 4; nj++) {
                int r = wn + nj*8 + gID;
                bfr[nj][0] = *(const uint32_t*)&Bs[r * ASTR + ks + 2*tig];
                bfr[nj][1] = *(const uint32_t*)&Bs[r * ASTR + ks + 2*tig + 8];
            }
#pragma unroll
            for (int mi = 0; mi < 2; mi++)
#pragma unroll
                for (int nj = 0; nj < 4; nj++)
                    mma16816(acc[mi][nj], af[mi][0], af[mi][1], af[mi][2], af[mi][3],
                             bfr[nj][0], bfr[nj][1]);
        }
        __syncthreads();
    }

#pragma unroll
    for (int mi = 0; mi < 2; mi++)
#pragma unroll
    for (int nj = 0; nj < 4; nj++) {
        int m = m0 + wm + mi*16 + gID;
        int n = n0 + wn + nj*8 + 2*tig;
        float* a = acc[mi][nj];
#pragma unroll
        for (int half = 0; half < 2; half++) {
            int mm = m + half * 8;
            float v0 = a[half*2 + 0], v1 = a[half*2 + 1];
            if (MODE == 1 || MODE == 2) {
                v0 = fmaxf(fmaf(v0, sc[n] * BNF, bi[n]), 0.f);
                v1 = fmaxf(fmaf(v1, sc[n+1] * BNF, bi[n+1]), 0.f);
            } else if (MODE == 3) {
                v0 += bi[n]; v1 += bi[n+1];
            } else if (MODE == 4) {
                const float2 e = *(const float2*)&extra[(long long)mm * N + n];
                v0 = fmaf(v0, 0.25f, e.x);
                v1 = fmaf(v1, 0.25f, e.y);
            }
            long long o = (long long)mm * N + n;
            *(float2*)&outf[o] = make_float2(v0, v1);
            if (MODE == 1) {
                bf16 h0, l0b, h1, l1b;
                split_bf(v0, h0, l0b);
                split_bf(v1, h1, l1b);
                __nv_bfloat162 hh; hh.x = h0; hh.y = h1;
                __nv_bfloat162 ll; ll.x = l0b; ll.y = l1b;
                *(__nv_bfloat162*)&ohi[o] = hh;
                *(__nv_bfloat162*)&olo[o] = ll;
            }
        }
    }
}

// ---------------- xproj (SIMT): proj = xm @ Wperm.T ---------------------------
__global__ void __launch_bounds__(192) gemm_xproj()
{
    __shared__ float As[16][132];
    __shared__ float Bs[16][52];
    int tid = threadIdx.x;
    int zb = blockIdx.y;
    int m0 = blockIdx.x * 128;
    const float* Ab = g_xm + (long long)zb * LL * DI;
    const float* aptr = Ab + (long long)(m0 + tid) * DI;
    int bn = tid >> 2, bk = (tid & 3) * 4;
    const float* bptr = g_xpw + bn * DI + bk;
    int ty = tid / 12, txx = tid % 12;

    float4 pa[4], pbv;
    if (tid < 128) {
#pragma unroll
        for (int j = 0; j < 4; j++) pa[j] = ((const float4*)aptr)[j];
    }
    pbv = *(const float4*)bptr;

    float acc[8][4] = {};
    for (int k0 = 0; k0 < DI; k0 += 16) {
        if (tid < 128) {
#pragma unroll
            for (int j = 0; j < 4; j++) {
                As[j*4+0][tid] = pa[j].x;
                As[j*4+1][tid] = pa[j].y;
                As[j*4+2][tid] = pa[j].z;
                As[j*4+3][tid] = pa[j].w;
            }
        }
        Bs[bk+0][bn] = pbv.x; Bs[bk+1][bn] = pbv.y;
        Bs[bk+2][bn] = pbv.z; Bs[bk+3][bn] = pbv.w;
        __syncthreads();
        if (k0 + 16 < DI) {
            if (tid < 128) {
                const float* an = aptr + k0 + 16;
#pragma unroll
                for (int j = 0; j < 4; j++) pa[j] = ((const float4*)an)[j];
            }
            pbv = *(const float4*)(bptr + k0 + 16);
        }
#pragma unroll
        for (int k = 0; k < 16; k++) {
            float4 a0 = *(const float4*)&As[k][ty*8];
            float4 a1 = *(const float4*)&As[k][ty*8+4];
            float4 b4 = *(const float4*)&Bs[k][txx*4];
            float a[8] = {a0.x,a0.y,a0.z,a0.w,a1.x,a1.y,a1.z,a1.w};
            float bv[4] = {b4.x,b4.y,b4.z,b4.w};
#pragma unroll
            for (int i = 0; i < 8; i++)
#pragma unroll
                for (int j = 0; j < 4; j++)
                    acc[i][j] = fmaf(a[i], bv[j], acc[i][j]);
        }
        __syncthreads();
    }
#pragma unroll
    for (int i = 0; i < 8; i++) {
        int m = m0 + ty*8 + i;
        *(float4*)(g_projm + ((long long)zb * LL + m) * 48 + txx*4) =
            make_float4(acc[i][0], acc[i][1], acc[i][2], acc[i][3]);
    }
}

// ------- layernorm over c (rows contiguous), emits xn hi/lo -------------------
__global__ void __launch_bounds__(256) ln_k(const float* __restrict__ lng,
                                            const float* __restrict__ lnb)
{
    int w = threadIdx.x >> 5, lane = threadIdx.x & 31;
    int tok = blockIdx.x * 8 + w;
    const float* xp = g_xred + (long long)tok * CC;
    float4 v0 = *(const float4*)(xp + lane*4);
    float4 v1 = *(const float4*)(xp + 128 + lane*4);
    float s = v0.x+v0.y+v0.z+v0.w + v1.x+v1.y+v1.z+v1.w;
    float ss = v0.x*v0.x+v0.y*v0.y+v0.z*v0.z+v0.w*v0.w
             + v1.x*v1.x+v1.y*v1.y+v1.z*v1.z+v1.w*v1.w;
#pragma unroll
    for (int o = 16; o; o >>= 1) {
        s  += __shfl_xor_sync(0xffffffffu, s, o);
        ss += __shfl_xor_sync(0xffffffffu, ss, o);
    }
    float mu = s * (1.f/CC);
    float rstd = rsqrtf(ss * (1.f/CC) - mu*mu + 1e-5f);
    float4 g0 = *(const float4*)(lng + lane*4);
    float4 g1 = *(const float4*)(lng + 128 + lane*4);
    float4 b0 = *(const float4*)(lnb + lane*4);
    float4 b1 = *(const float4*)(lnb + 128 + lane*4);
    float vals[8] = {v0.x,v0.y,v0.z,v0.w, v1.x,v1.y,v1.z,v1.w};
    float gs[8] = {g0.x,g0.y,g0.z,g0.w, g1.x,g1.y,g1.z,g1.w};
    float bs[8] = {b0.x,b0.y,b0.z,b0.w, b1.x,b1.y,b1.z,b1.w};
    bf16 hi[8], lo[8];
#pragma unroll
    for (int i = 0; i < 8; i++) {
        float xn = (vals[i] - mu) * rstd * gs[i] + bs[i];
        split_bf(xn, hi[i], lo[i]);
    }
    long long base = (long long)tok * CC;
    *(uint2*)&g_xnhi[base + lane*4] = *(uint2*)&hi[0];
    *(uint2*)&g_xnhi[base + 128 + lane*4] = *(uint2*)&hi[4];
    *(uint2*)&g_xnlo[base + lane*4] = *(uint2*)&lo[0];
    *(uint2*)&g_xnlo[base + 128 + lane*4] = *(uint2*)&lo[4];
}

// -------- causal depthwise conv1d + silu (scan order) -------------------------
#define CCT 64
__global__ void __launch_bounds__(512) conv1d_k(const float* __restrict__ cw,
                                                const float* __restrict__ cb)
{
    __shared__ int sl[CCT + 3];
    int d = threadIdx.x;
    int t0 = blockIdx.x * CCT;
    int b = blockIdx.y;
    int dir = blockIdx.z;
    if (d < CCT + 3) {
        int tt = t0 - 3 + d;
        sl[d] = (tt >= 0) ? g_map[dir * LL + tt] : 0;
    }
    __syncthreads();
    float w0 = cw[d*4+0], w1 = cw[d*4+1], w2 = cw[d*4+2], w3 = cw[d*4+3];
    float bias = cb[d];
    const float* xzb = g_xz + (long long)b * LL * 1024 + d;
    float x0 = 0.f, x1 = 0.f, x2 = 0.f;
    if (t0 > 0) {
        x0 = xzb[(long long)sl[0] * 1024];
        x1 = xzb[(long long)sl[1] * 1024];
        x2 = xzb[(long long)sl[2] * 1024];
    }
    float xn = xzb[(long long)sl[3] * 1024];
    float* yo = &g_xm[(((long long)dir * BB + b) * LL + t0) * DI + d];
    for (int i = 0; i < CCT; i++) {
        float xnn = (i + 1 < CCT) ? xzb[(long long)sl[i + 4] * 1024] : 0.f;
        float s = bias + w0*x0 + w1*x1 + w2*x2 + w3*xn;
        yo[(long long)i * DI] = silu_f(s);
        x0 = x1; x1 = x2; x2 = xn; xn = xnn;
    }
}

// ---------- dt = softplus(proj[:,:16] @ dt_w.T + dt_b) ------------------------
#define DTT 16
__global__ void __launch_bounds__(512) dt_k(const float* __restrict__ dtbias)
{
    __shared__ float pr[DTT][16];
    int d = threadIdx.x;
    int t0 = blockIdx.x * DTT;
    int b = blockIdx.y, dir = blockIdx.z;
    long long row0 = ((long long)dir * BB + b) * LL + t0;
    if (d < DTT * 16) {
        int ti = d >> 4, r = d & 15;
        pr[ti][r] = g_projm[(row0 + ti) * 48 + r];
    }
    float wreg[16];
#pragma unroll
    for (int r = 0; r < 16; r++) wreg[r] = g_dtwT[r * DI + d];
    float bias = dtbias[d];
    __syncthreads();
    float* out = &g_dtb[row0 * DI + d];
#pragma unroll 4
    for (int t = 0; t < DTT; t++) {
        float acc = bias;
#pragma unroll
        for (int r = 0; r < 16; r++) acc = fmaf(pr[t][r], wreg[r], acc);
        float dt = (acc > 15.f) ? acc : log1pf(expf(acc));
        out[(long long)t * DI] = dt;
    }
}

// -------- selective scan: warp = 4 channels x 8 lanes, 2 states/lane ----------
__global__ void __launch_bounds__(128) scan_k(const float* __restrict__ A_log,
                                              const float* __restrict__ Dp)
{
    const float L2E = 1.4426950408889634f;
    int tid = threadIdx.x;
    int lane = tid & 31;
    int gwarp = blockIdx.x * 4 + (tid >> 5);          // 0..1023
    int dir = gwarp >> 8;
    int b = (gwarp >> 7) & 1;
    int d = ((gwarp & 127) << 2) | (lane >> 3);       // 4 channels per warp
    int s = lane & 7;                                 // states s and s+8

    // fold log2(e) into A so we can use exp2f (single MUFU)
    float Av0 = -expf(A_log[d * 16 + s]) * L2E;
    float Av1 = -expf(A_log[d * 16 + s + 8]) * L2E;
    float Dv = Dp[d];
    long long dbase = ((long long)dir * BB + b) * LL;
    const float* pdt = g_dtb + dbase * DI + d;
    const float* pxm = g_xm + dbase * DI + d;
    const float2* pbc0 = reinterpret_cast<const float2*>(g_projm) + dbase * 24 + 8 + s;
    const float2* pbc1 = pbc0 + 8;
    bf16* py = g_y + dbase * DI + d;

    const int PF = 8;
    float f_dt[PF], f_x[PF];
    float2 f_b0[PF], f_b1[PF];
#pragma unroll
    for (int i = 0; i < PF; i++) {
        f_dt[i] = pdt[i * DI];
        f_x[i]  = pxm[i * DI];
        f_b0[i] = pbc0[i * 24];
        f_b1[i] = pbc1[i * 24];
    }
    const float* qdt = pdt + PF * DI;
    const float* qxm = pxm + PF * DI;
    const float2* qb0 = pbc0 + PF * 24;
    const float2* qb1 = pbc1 + PF * 24;

    float h0 = 0.f, h1 = 0.f;
    for (int t0 = 0; t0 < LL; t0 += PF) {
        bool pf = (t0 + PF < LL);
#pragma unroll
        for (int i = 0; i < PF; i++) {
            float dtv = f_dt[i], xv = f_x[i];
            float B0 = f_b0[i].x, C0 = f_b0[i].y;
            float B1 = f_b1[i].x, C1 = f_b1[i].y;
            if (pf) {
                f_dt[i] = qdt[i * DI];
                f_x[i]  = qxm[i * DI];
                f_b0[i] = qb0[i * 24];
                f_b1[i] = qb1[i * 24];
            }
            float dtx = dtv * xv;
            h0 = fmaf(exp2f(dtv * Av0), h0, dtx * B0);
            h1 = fmaf(exp2f(dtv * Av1), h1, dtx * B1);
            float part = fmaf(h0, C0, h1 * C1);
            part += __shfl_xor_sync(0xffffffffu, part, 1);
            part += __shfl_xor_sync(0xffffffffu, part, 2);
            part += __shfl_xor_sync(0xffffffffu, part, 4);
            if (s == 0) py[i * DI] = __float2bfloat16(fmaf(Dv, xv, part));
        }
        qdt += PF * DI; qxm += PF * DI; qb0 += PF * 24; qb1 += PF * 24; py += PF * DI;
    }
}

// ----- gather 4 dirs to natural order, silu(z) gate, emit ysum hi/lo ----------
__global__ void ysum_k()
{
    long long i = (long long)blockIdx.x * blockDim.x + threadIdx.x;
    if (i >= (long long)BL * DI) return;
    int d = (int)(i & (DI - 1));
    int l = (int)((i / DI) % LL);
    int b = (int)(i / ((long long)LL * DI));
    int t2 = (l % WW) * HH + l / WW;
    const long long st = (long long)BB * LL * DI;
    long long bb = (long long)b * LL * DI;
    float y = __bfloat162float(g_y[bb + (long long)l * DI + d])
            + __bfloat162float(g_y[st + bb + (long long)(LL - 1 - l) * DI + d])
            + __bfloat162float(g_y[2 * st + bb + (long long)t2 * DI + d])
            + __bfloat162float(g_y[3 * st + bb + (long long)(LL - 1 - t2) * DI + d]);
    float z = g_xz[((long long)b * LL + l) * 1024 + DI + d];
    float v = y * silu_f(z);
    bf16 h, lo;
    split_bf(v, h, lo);
    long long o = ((long long)b * LL + l) * DI + d;
    g_yshi[o] = h; g_yslo[o] = lo;
}

// ------------- depthwise 1x7 + 7x1, smem-tiled token-major --------------------
__global__ void __launch_bounds__(256) dwconv_tile_k(
    const float* __restrict__ wh, const float* __restrict__ wv,
    const float* __restrict__ hg, const float* __restrict__ hb,
    const float* __restrict__ vg, const float* __restrict__ vb)
{
    __shared__ float sm[14*14*32];
    int b = blockIdx.z;
    int c0 = blockIdx.y * 32;
    int tx0 = (blockIdx.x % 6) * 8, ty0 = (blockIdx.x / 6) * 8;
    int tid = threadIdx.x;

    for (int e = tid; e < 14*14*32; e += 256) {
        int c = e & 31;
        int rest = e >> 5;
        int xx = rest % 14, yy = rest / 14;
        int y = ty0 + yy - 3, x = tx0 + xx - 3;
        float v = 0.f;
        if (y >= 0 && y < HH && x >= 0 && x < WW)
            v = g_p[((long long)b * HWW + y * WW + x) * CC + c0 + c];
        sm[e] = v;
    }
    __syncthreads();

    int c = tid & 31, sy = tid >> 5;
    int cc = c0 + c;
    float whr[7], wvr[7];
#pragma unroll
    for (int j = 0; j < 7; j++) { whr[j] = wh[cc*7 + j]; wvr[j] = wv[cc*7 + j]; }
    float hgv = hg[cc] * BNF, hbv = hb[cc];
    float vgv = vg[cc] * BNF, vbv = vb[cc];

#pragma unroll
    for (int sx = 0; sx < 8; sx++) {
        float sh = 0.f, sv = 0.f;
#pragma unroll
        for (int j = 0; j < 7; j++) {
            sh = fmaf(sm[((sy+3)*14 + sx+j)*32 + c], whr[j], sh);
            sv = fmaf(sm[((sy+j)*14 + sx+3)*32 + c], wvr[j], sv);
        }
        float rh = fmaxf(fmaf(sh, hgv, hbv), 0.f);
        float rv = fmaxf(fmaf(sv, vgv, vbv), 0.f);
        bf16 h, lo;
        split_bf(rh + rv, h, lo);
        long long o = ((long long)b * HWW + (ty0+sy) * WW + tx0 + sx) * CC + cc;
        g_hvhi[o] = h; g_hvlo[o] = lo;
    }
}

// ------------------------- SE head (token-major) ------------------------------
__global__ void mean1_k()
{
    int blk = blockIdx.x, b = blockIdx.y, c = threadIdx.x;
    float s = 0.f;
    for (int i = 0; i < 64; i++) {
        long long idx = ((long long)b * HWW + blk * 64 + i) * CC + c;
        s += g_featloc[idx] + g_featglob[idx];
    }
    g_msum[(b * 36 + blk) * CC + c] = s;
}
__global__ void mean2_k()
{
    int b = blockIdx.x, c = threadIdx.x;
    float s = 0.f;
    for (int i = 0; i < 36; i++) s += g_msum[(b * 36 + i) * CC + c];
    g_sv[b * CC + c] = s / (float)HWW;
}

__global__ void fc_k(const float* __restrict__ fc1, const float* __restrict__ fc2)
{
    int b = blockIdx.x;
    __shared__ float ss[CC], tt[16];
    int tid = threadIdx.x;
    ss[tid] = g_sv[b * CC + tid];
    __syncthreads();
    if (tid < 16) {
        float a = 0.f;
        for (int c = 0; c < CC; c++) a += ss[c] * fc1[tid * CC + c];
        tt[tid] = fmaxf(a, 0.f);
    }
    __syncthreads();
    float z0 = 0.f, z1 = 0.f;
#pragma unroll
    for (int m = 0; m < 16; m++) {
        z0 += tt[m] * fc2[tid * 16 + m];
        z1 += tt[m] * fc2[(CC + tid) * 16 + m];
    }
    float mx = fmaxf(z0, z1);
    float e0 = expf(z0 - mx), e1 = expf(z1 - mx);
    float w0 = e0 / (e0 + e1);
    g_wv[b * 2 * CC + tid] = w0;
    g_wv[b * 2 * CC + CC + tid] = 1.f - w0;
}

// ---- final combine + transpose [l][c] -> out[b][c][hw] -----------------------
__global__ void final_trans_k(float* __restrict__ out)
{
    __shared__ float tile[32][33];
    int b = blockIdx.z;
    int l0 = blockIdx.x * 32, c0 = blockIdx.y * 32;
    int tx = threadIdx.x, ty = threadIdx.y;
    float w0 = g_wv[b * 2 * CC + c0 + tx];
    float w1 = g_wv[b * 2 * CC + CC + c0 + tx];
#pragma unroll
    for (int i = 0; i < 4; i++) {
        long long idx = ((long long)b * HWW + l0 + ty + i*8) * CC + c0 + tx;
        tile[ty + i*8][tx] = w0 * g_featloc[idx] + w1 * g_featglob[idx];
    }
    __syncthreads();
#pragma unroll
    for (int i = 0; i < 4; i++)
        out[((long long)b * CC + c0 + ty + i*8) * HWW + l0 + tx] = tile[tx][ty + i*8];
}

// ------------------------- launch ---------------------------------------------
extern "C" void kernel_launch(void* const* d_in, const int* in_sizes, int n_in,
                              void* d_out, int out_size)
{
    const float* x        = (const float*)d_in[0];
    const float* reduce_w = (const float*)d_in[1];
    const float* bn0_g    = (const float*)d_in[2];
    const float* bn0_b    = (const float*)d_in[3];
    const float* proj_w   = (const float*)d_in[4];
    const float* bn1_g    = (const float*)d_in[5];
    const float* bn1_b    = (const float*)d_in[6];
    const float* dwh_w    = (const float*)d_in[7];
    const float* bnh_g    = (const float*)d_in[8];
    const float* bnh_b    = (const float*)d_in[9];
    const float* dwv_w    = (const float*)d_in[10];
    const float* bnv_g    = (const float*)d_in[11];
    const float* bnv_b    = (const float*)d_in[12];
    const float* fus_w    = (const float*)d_in[13];
    const float* fus_b    = (const float*)d_in[14];
    const float* ln_g     = (const float*)d_in[15];
    const float* ln_b     = (const float*)d_in[16];
    const float* in_w     = (const float*)d_in[17];
    const float* conv_w   = (const float*)d_in[18];
    const float* conv_b   = (const float*)d_in[19];
    const float* xproj_w  = (const float*)d_in[20];
    const float* dt_w     = (const float*)d_in[21];
    const float* dt_b     = (const float*)d_in[22];
    const float* A_log    = (const float*)d_in[23];
    const float* Dp       = (const float*)d_in[24];
    const float* out_w    = (const float*)d_in[25];
    const float* fc1_w    = (const float*)d_in[26];
    const float* fc2_w    = (const float*)d_in[27];

    bf16 *xthi, *xtlo, *rwhi, *rwlo, *pwhi, *pwlo, *fwhi, *fwlo, *owhi, *owlo,
         *xrhi, *xrlo, *hvhi, *hvlo, *yshi, *yslo;
    float *xred, *p, *featloc, *featglob;
    cudaGetSymbolAddress((void**)&xthi, g_xthi);  cudaGetSymbolAddress((void**)&xtlo, g_xtlo);
    cudaGetSymbolAddress((void**)&rwhi, g_rwhi);  cudaGetSymbolAddress((void**)&rwlo, g_rwlo);
    cudaGetSymbolAddress((void**)&pwhi, g_pwhi);  cudaGetSymbolAddress((void**)&pwlo, g_pwlo);
    cudaGetSymbolAddress((void**)&fwhi, g_fwhi);  cudaGetSymbolAddress((void**)&fwlo, g_fwlo);
    cudaGetSymbolAddress((void**)&owhi, g_owhi);  cudaGetSymbolAddress((void**)&owlo, g_owlo);
    cudaGetSymbolAddress((void**)&xrhi, g_xrhi);  cudaGetSymbolAddress((void**)&xrlo, g_xrlo);
    cudaGetSymbolAddress((void**)&hvhi, g_hvhi);  cudaGetSymbolAddress((void**)&hvlo, g_hvlo);
    cudaGetSymbolAddress((void**)&yshi, g_yshi);  cudaGetSymbolAddress((void**)&yslo, g_yslo);
    cudaGetSymbolAddress((void**)&xred, g_xred);
    cudaGetSymbolAddress((void**)&p, g_p);
    cudaGetSymbolAddress((void**)&featloc, g_featloc);
    cudaGetSymbolAddress((void**)&featglob, g_featglob);

    // 0) one-time prep
    init_misc_k<<<2560, 256>>>(dt_w, xproj_w, reduce_w, proj_w, fus_w, in_w, out_w);
    // 1) input transpose + split
    trans_in_k<<<dim3(HWW/32, CIN/32, BB), dim3(32, 8)>>>(x);
    // 2) reduce [tensor]
    gemm_t3s<1><<<dim3(4, 72), 128>>>(xthi, xtlo, rwhi, rwlo,
        xred, xrhi, xrlo, CC, CIN, bn0_g, bn0_b, (const float*)0);
    // 3) layernorm -> xn hi/lo
    ln_k<<<BL/8, 256>>>(ln_g, ln_b);
    // 4) in_proj [tensor big]
    gemm_inproj_t3<<<dim3(8, 36), 256>>>();
    // 5) causal conv1d + silu -> scan-ordered xm
    conv1d_k<<<dim3(LL/CCT, BB, 4), 512>>>(conv_w, conv_b);
    // 6) xproj (SIMT)
    gemm_xproj<<<dim3(18, 8), 192>>>();
    // 7) dt
    dt_k<<<dim3(LL/DTT, BB, 4), 512>>>(dt_b);
    // 8) selective scan (4 channels/warp, 2 states/lane)
    scan_k<<<256, 128>>>(A_log, Dp);
    // 9) gather + gate -> ysum hi/lo
    ysum_k<<<(BL*DI + 255)/256, 256>>>();
    // 10) out_proj [tensor]
    gemm_t3s<4><<<dim3(4, 72), 128>>>(yshi, yslo, owhi, owlo,
        featglob, (bf16*)0, (bf16*)0, CC, DI, (const float*)0, (const float*)0, xred);
    // 11) proj [tensor]
    gemm_t3s<2><<<dim3(4, 72), 128>>>(xrhi, xrlo, pwhi, pwlo,
        p, (bf16*)0, (bf16*)0, CC, CC, bn1_g, bn1_b, (const float*)0);
    // 12) depthwise h+v (smem-tiled)
    dwconv_tile_k<<<dim3(36, 8, BB), 256>>>(dwh_w, dwv_w, bnh_g, bnh_b, bnv_g, bnv_b);
    // 13) fus [tensor]
    gemm_t3s<3><<<dim3(4, 72), 128>>>(hvhi, hvlo, fwhi, fwlo,
        featloc, (bf16*)0, (bf16*)0, CC, CC, (const float*)0, fus_b, (const float*)0);
    // 14-16) SE head + final combine/transpose
    mean1_k<<<dim3(36, BB), 256>>>();
    mean2_k<<<BB, 256>>>();
    fc_k<<<BB, 256>>>(fc1_w, fc2_w);
    final_trans_k<<<dim3(HWW/32, CC/32, BB), dim3(32, 8)>>>((float*)d_out);
}

// round 16
// speedup vs baseline: 1.4352x; 1.4352x over previous
#include <cuda_runtime.h>
#include <cuda_bf16.h>
#include <stdint.h>
#include <math.h>

#define BB  2
#define CIN 512
#define CC  256
#define HH  48
#define WW  48
#define HWW 2304
#define LL  2304
#define DI  512
#define BL  (BB*LL)
#define BNF 0.9999950000374997f

typedef __nv_bfloat16 bf16;

// ------------------------- static scratch (no allocs) -------------------------
__device__ __align__(256) float g_xred[BL*CC];        // token-major
__device__ __align__(256) float g_p[BL*CC];
__device__ __align__(256) float g_featloc[BL*CC];
__device__ __align__(256) float g_featglob[BL*CC];
__device__ __align__(256) float g_xz[BL*2*DI];
__device__ __align__(256) float g_xm[4*BL*DI];
__device__ __align__(256) float g_projm[4*BL*48];
__device__ __align__(256) float g_dtb[4*BL*DI];
__device__ __align__(256) bf16  g_y[4*BL*DI];
// bf16 split activations
__device__ __align__(256) bf16 g_xthi[BL*CIN],  g_xtlo[BL*CIN];
__device__ __align__(256) bf16 g_xrhi[BL*CC],   g_xrlo[BL*CC];
__device__ __align__(256) bf16 g_xnhi[BL*CC],   g_xnlo[BL*CC];
__device__ __align__(256) bf16 g_hvhi[BL*CC],   g_hvlo[BL*CC];
__device__ __align__(256) bf16 g_yshi[BL*DI],   g_yslo[BL*DI];
// bf16 split weights
__device__ __align__(256) bf16 g_rwhi[CC*CIN],  g_rwlo[CC*CIN];
__device__ __align__(256) bf16 g_pwhi[CC*CC],   g_pwlo[CC*CC];
__device__ __align__(256) bf16 g_fwhi[CC*CC],   g_fwlo[CC*CC];
__device__ __align__(256) bf16 g_iwhi[2*DI*CC], g_iwlo[2*DI*CC];
__device__ __align__(256) bf16 g_owhi[CC*DI],   g_owlo[CC*DI];
// misc
__device__ __align__(256) float g_dtwT[16*DI];
__device__ __align__(256) float g_xpw[48*DI];
__device__ __align__(256) int   g_map[4*LL];
__device__ __align__(256) float g_msum[BB*36*CC];
__device__ __align__(256) float g_sv[BB*CC];
__device__ __align__(256) float g_wv[BB*2*CC];

__device__ __forceinline__ int seq_map(int dir, int t) {
    if (dir == 0) return t;
    if (dir == 1) return LL - 1 - t;
    int u = (dir == 2) ? t : (LL - 1 - t);
    int h = u % HH, w = u / HH;
    return h * WW + w;
}
__device__ __forceinline__ float silu_f(float x) { return x / (1.f + __expf(-x)); }
__device__ __forceinline__ float ex2f(float x) {
    float y;
    asm("ex2.approx.f32 %0, %1;" : "=f"(y) : "f"(x));
    return y;
}
__device__ __forceinline__ void split_bf(float v, bf16& h, bf16& l) {
    h = __float2bfloat16(v);
    l = __float2bfloat16(v - __bfloat162float(h));
}

// ------------------ one-time prep ---------------------------------------------
__global__ void init_misc_k(const float* __restrict__ dtw, const float* __restrict__ xpw,
                            const float* __restrict__ rw, const float* __restrict__ pw,
                            const float* __restrict__ fw, const float* __restrict__ iw,
                            const float* __restrict__ ow)
{
    int i = blockIdx.x * 256 + threadIdx.x;
    if (i < 16 * DI) {
        int dd = i >> 4, r = i & 15;
        g_dtwT[r * DI + dd] = dtw[i];
    }
    if (i < 4 * LL) g_map[i] = seq_map(i / LL, i % LL);
    if (i < 48 * DI) {
        int j = i >> 9, k = i & 511;
        int src = (j < 16) ? j
                : (((j - 16) & 1) ? 32 + ((j - 16) >> 1) : 16 + ((j - 16) >> 1));
        g_xpw[i] = xpw[src * DI + k];
    }
    int o = i;
    if (o < CC*CIN) { split_bf(rw[o], g_rwhi[o], g_rwlo[o]); return; }
    o -= CC*CIN;
    if (o < CC*CC)  { split_bf(pw[o], g_pwhi[o], g_pwlo[o]); return; }
    o -= CC*CC;
    if (o < CC*CC)  { split_bf(fw[o], g_fwhi[o], g_fwlo[o]); return; }
    o -= CC*CC;
    if (o < 2*DI*CC){ split_bf(iw[o], g_iwhi[o], g_iwlo[o]); return; }
    o -= 2*DI*CC;
    if (o < CC*DI)  { split_bf(ow[o], g_owhi[o], g_owlo[o]); return; }
}

// ---------- input transpose: x[b][cin][hw] -> xT hi/lo ------------------------
__global__ void trans_in_k(const float* __restrict__ x)
{
    __shared__ float tile[32][33];
    int b = blockIdx.z;
    int l0 = blockIdx.x * 32, c0 = blockIdx.y * 32;
    int tx = threadIdx.x, ty = threadIdx.y;      // (32,8)
#pragma unroll
    for (int i = 0; i < 4; i++)
        tile[ty + i*8][tx] = x[((long long)b*CIN + c0 + ty + i*8) * HWW + l0 + tx];
    __syncthreads();
#pragma unroll
    for (int i = 0; i < 4; i++) {
        long long o = ((long long)b*HWW + l0 + ty + i*8) * CIN + c0 + tx;
        bf16 h, l;
        split_bf(tile[tx][ty + i*8], h, l);
        g_xthi[o] = h; g_xtlo[o] = l;
    }
}

// ======================= mma primitive ========================================
#define ASTR 40
__device__ __forceinline__ void mma16816(float* d, uint32_t a0, uint32_t a1,
                                         uint32_t a2, uint32_t a3,
                                         uint32_t b0, uint32_t b1)
{
    asm volatile(
        "mma.sync.aligned.m16n8k16.row.col.f32.bf16.bf16.f32 "
        "{%0,%1,%2,%3}, {%4,%5,%6,%7}, {%8,%9}, {%0,%1,%2,%3};\n"
        : "+f"(d[0]), "+f"(d[1]), "+f"(d[2]), "+f"(d[3])
        : "r"(a0), "r"(a1), "r"(a2), "r"(a3), "r"(b0), "r"(b1));
}

// ---------------- big 128x128 tensor GEMM (in_proj) ---------------------------
__global__ void __launch_bounds__(256) gemm_inproj_t3()
{
    __shared__ bf16 As[128 * ASTR];
    __shared__ bf16 Bs[128 * ASTR];
    const int K = CC;
    const int N = 2 * DI;
    int tid = threadIdx.x;
    int warp = tid >> 5, lane = tid & 31;
    int gID = lane >> 2, tig = lane & 3;
    int wm = (warp >> 2) * 64, wn = (warp & 3) * 32;
    int m0 = blockIdx.y * 128, n0 = blockIdx.x * 128;

    int u0 = tid, u1 = tid + 256;
    int ar0 = u0 >> 2, ac0 = (u0 & 3) * 8;
    int ar1 = u1 >> 2, ac1 = (u1 & 3) * 8;

    uint4 ra[2], rb[2];
    ra[0] = *(const uint4*)(g_xnhi + (long long)(m0 + ar0) * K + ac0);
    ra[1] = *(const uint4*)(g_xnhi + (long long)(m0 + ar1) * K + ac1);
    rb[0] = *(const uint4*)(g_iwhi + (long long)(n0 + ar0) * K + ac0);
    rb[1] = *(const uint4*)(g_iwhi + (long long)(n0 + ar1) * K + ac1);

    float acc[4][4][4] = {};
    const int G = 24;

    for (int g = 0; g < G; g++) {
        *(uint4*)&As[ar0 * ASTR + ac0] = ra[0];
        *(uint4*)&As[ar1 * ASTR + ac1] = ra[1];
        *(uint4*)&Bs[ar0 * ASTR + ac0] = rb[0];
        *(uint4*)&Bs[ar1 * ASTR + ac1] = rb[1];
        __syncthreads();
        int gn = g + 1;
        if (gn < G) {
            int pass = gn >> 3;
            int kk = (gn & 7) * 32;
            const bf16* Ag = (pass == 1) ? g_xnlo : g_xnhi;
            const bf16* Bg = (pass == 2) ? g_iwlo : g_iwhi;
            ra[0] = *(const uint4*)(Ag + (long long)(m0 + ar0) * K + kk + ac0);
            ra[1] = *(const uint4*)(Ag + (long long)(m0 + ar1) * K + kk + ac1);
            rb[0] = *(const uint4*)(Bg + (long long)(n0 + ar0) * K + kk + ac0);
            rb[1] = *(const uint4*)(Bg + (long long)(n0 + ar1) * K + kk + ac1);
        }
#pragma unroll
        for (int ks = 0; ks < 32; ks += 16) {
            uint32_t af[4][4], bfr[4][2];
#pragma unroll
            for (int mi = 0; mi < 4; mi++) {
                int r = wm + mi*16 + gID;
                af[mi][0] = *(const uint32_t*)&As[r * ASTR + ks + 2*tig];
                af[mi][1] = *(const uint32_t*)&As[(r+8) * ASTR + ks + 2*tig];
                af[mi][2] = *(const uint32_t*)&As[r * ASTR + ks + 2*tig + 8];
                af[mi][3] = *(const uint32_t*)&As[(r+8) * ASTR + ks + 2*tig + 8];
            }
#pragma unroll
            for (int nj = 0; nj < 4; nj++) {
                int r = wn + nj*8 + gID;
                bfr[nj][0] = *(const uint32_t*)&Bs[r * ASTR + ks + 2*tig];
                bfr[nj][1] = *(const uint32_t*)&Bs[r * ASTR + ks + 2*tig + 8];
            }
#pragma unroll
            for (int mi = 0; mi < 4; mi++)
#pragma unroll
                for (int nj = 0; nj < 4; nj++)
                    mma16816(acc[mi][nj], af[mi][0], af[mi][1], af[mi][2], af[mi][3],
                             bfr[nj][0], bfr[nj][1]);
        }
        __syncthreads();
    }

#pragma unroll
    for (int mi = 0; mi < 4; mi++)
#pragma unroll
    for (int nj = 0; nj < 4; nj++) {
        int m = m0 + wm + mi*16 + gID;
        int n = n0 + wn + nj*8 + 2*tig;
        float* a = acc[mi][nj];
#pragma unroll
        for (int half = 0; half < 2; half++) {
            int mm = m + half * 8;
            *(float2*)&g_xz[(long long)mm * N + n] = make_float2(a[half*2], a[half*2+1]);
        }
    }
}

// ---------------- small 64x64 tensor GEMM (4 warps, warp 32x32) ---------------
template<int MODE>
__global__ void __launch_bounds__(128) gemm_t3s(
    const bf16* __restrict__ Ahi, const bf16* __restrict__ Alo,
    const bf16* __restrict__ Bhi, const bf16* __restrict__ Blo,
    float* __restrict__ outf, bf16* __restrict__ ohi, bf16* __restrict__ olo,
    int N, int K,
    const float* __restrict__ sc, const float* __restrict__ bi,
    const float* __restrict__ extra)
{
    __shared__ bf16 As[64 * ASTR];
    __shared__ bf16 Bs[64 * ASTR];
    int tid = threadIdx.x;
    int warp = tid >> 5, lane = tid & 31;
    int gID = lane >> 2, tig = lane & 3;
    int wm = (warp >> 1) * 32, wn = (warp & 1) * 32;
    int m0 = blockIdx.y * 64, n0 = blockIdx.x * 64;

    int ar = tid >> 2;
    int ac = (tid & 3) * 8;

    int K32 = K >> 5;
    int G = 3 * K32;

    uint4 ra[2], rb[2];
    ra[0] = *(const uint4*)(Ahi + (long long)(m0 + ar) * K + ac);
    ra[1] = *(const uint4*)(Ahi + (long long)(m0 + ar + 32) * K + ac);
    rb[0] = *(const uint4*)(Bhi + (long long)(n0 + ar) * K + ac);
    rb[1] = *(const uint4*)(Bhi + (long long)(n0 + ar + 32) * K + ac);

    float acc[2][4][4] = {};

    for (int g = 0; g < G; g++) {
        *(uint4*)&As[ar * ASTR + ac] = ra[0];
        *(uint4*)&As[(ar + 32) * ASTR + ac] = ra[1];
        *(uint4*)&Bs[ar * ASTR + ac] = rb[0];
        *(uint4*)&Bs[(ar + 32) * ASTR + ac] = rb[1];
        __syncthreads();
        int gn = g + 1;
        if (gn < G) {
            int pass = gn / K32;
            int kk = (gn - pass * K32) * 32;
            const bf16* Ag = (pass == 1) ? Alo : Ahi;
            const bf16* Bg = (pass == 2) ? Blo : Bhi;
            ra[0] = *(const uint4*)(Ag + (long long)(m0 + ar) * K + kk + ac);
            ra[1] = *(const uint4*)(Ag + (long long)(m0 + ar + 32) * K + kk + ac);
            rb[0] = *(const uint4*)(Bg + (long long)(n0 + ar) * K + kk + ac);
            rb[1] = *(const uint4*)(Bg + (long long)(n0 + ar + 32) * K + kk + ac);
        }
#pragma unroll
        for (int ks = 0; ks < 32; ks += 16) {
            uint32_t af[2][4], bfr[4][2];
#pragma unroll
            for (int mi = 0; mi < 2; mi++) {
                int r = wm + mi*16 + gID;
                af[mi][0] = *(const uint32_t*)&As[r * ASTR + ks + 2*tig];
                af[mi][1] = *(const uint32_t*)&As[(r+8) * ASTR + ks + 2*tig];
                af[mi][2] = *(const uint32_t*)&As[r * ASTR + ks + 2*tig + 8];
                af[mi][3] = *(const uint32_t*)&As[(r+8) * ASTR + ks + 2*tig + 8];
            }
#pragma unroll
            for (int nj = 0; nj < 4; nj++) {
                int r = wn + nj*8 + gID;
                bfr[nj][0] = *(const uint32_t*)&Bs[r * ASTR + ks + 2*tig];
                bfr[nj][1] = *(const uint32_t*)&Bs[r * ASTR + ks + 2*tig + 8];
            }
#pragma unroll
            for (int mi = 0; mi < 2; mi++)
#pragma unroll
                for (int nj = 0; nj < 4; nj++)
                    mma16816(acc[mi][nj], af[mi][0], af[mi][1], af[mi][2], af[mi][3],
                             bfr[nj][0], bfr[nj][1]);
        }
        __syncthreads();
    }

#pragma unroll
    for (int mi = 0; mi < 2; mi++)
#pragma unroll
    for (int nj = 0; nj < 4; nj++) {
        int m = m0 + wm + mi*16 + gID;
        int n = n0 + wn + nj*8 + 2*tig;
        float* a = acc[mi][nj];
#pragma unroll
        for (int half = 0; half < 2; half++) {
            int mm = m + half * 8;
            float v0 = a[half*2 + 0], v1 = a[half*2 + 1];
            if (MODE == 1 || MODE == 2) {
                v0 = fmaxf(fmaf(v0, sc[n] * BNF, bi[n]), 0.f);
                v1 = fmaxf(fmaf(v1, sc[n+1] * BNF, bi[n+1]), 0.f);
            } else if (MODE == 3) {
                v0 += bi[n]; v1 += bi[n+1];
            } else if (MODE == 4) {
                const float2 e = *(const float2*)&extra[(long long)mm * N + n];
                v0 = fmaf(v0, 0.25f, e.x);
                v1 = fmaf(v1, 0.25f, e.y);
            }
            long long o = (long long)mm * N + n;
            *(float2*)&outf[o] = make_float2(v0, v1);
            if (MODE == 1) {
                bf16 h0, l0b, h1, l1b;
                split_bf(v0, h0, l0b);
                split_bf(v1, h1, l1b);
                __nv_bfloat162 hh; hh.x = h0; hh.y = h1;
                __nv_bfloat162 ll; ll.x = l0b; ll.y = l1b;
                *(__nv_bfloat162*)&ohi[o] = hh;
                *(__nv_bfloat162*)&olo[o] = ll;
            }
        }
    }
}

// ---------------- xproj (SIMT): proj = xm @ Wperm.T ---------------------------
__global__ void __launch_bounds__(192) gemm_xproj()
{
    __shared__ float As[16][132];
    __shared__ float Bs[16][52];
    int tid = threadIdx.x;
    int zb = blockIdx.y;
    int m0 = blockIdx.x * 128;
    const float* Ab = g_xm + (long long)zb * LL * DI;
    const float* aptr = Ab + (long long)(m0 + tid) * DI;
    int bn = tid >> 2, bk = (tid & 3) * 4;
    const float* bptr = g_xpw + bn * DI + bk;
    int ty = tid / 12, txx = tid % 12;

    float4 pa[4], pbv;
    if (tid < 128) {
#pragma unroll
        for (int j = 0; j < 4; j++) pa[j] = ((const float4*)aptr)[j];
    }
    pbv = *(const float4*)bptr;

    float acc[8][4] = {};
    for (int k0 = 0; k0 < DI; k0 += 16) {
        if (tid < 128) {
#pragma unroll
            for (int j = 0; j < 4; j++) {
                As[j*4+0][tid] = pa[j].x;
                As[j*4+1][tid] = pa[j].y;
                As[j*4+2][tid] = pa[j].z;
                As[j*4+3][tid] = pa[j].w;
            }
        }
        Bs[bk+0][bn] = pbv.x; Bs[bk+1][bn] = pbv.y;
        Bs[bk+2][bn] = pbv.z; Bs[bk+3][bn] = pbv.w;
        __syncthreads();
        if (k0 + 16 < DI) {
            if (tid < 128) {
                const float* an = aptr + k0 + 16;
#pragma unroll
                for (int j = 0; j < 4; j++) pa[j] = ((const float4*)an)[j];
            }
            pbv = *(const float4*)(bptr + k0 + 16);
        }
#pragma unroll
        for (int k = 0; k < 16; k++) {
            float4 a0 = *(const float4*)&As[k][ty*8];
            float4 a1 = *(const float4*)&As[k][ty*8+4];
            float4 b4 = *(const float4*)&Bs[k][txx*4];
            float a[8] = {a0.x,a0.y,a0.z,a0.w,a1.x,a1.y,a1.z,a1.w};
            float bv[4] = {b4.x,b4.y,b4.z,b4.w};
#pragma unroll
            for (int i = 0; i < 8; i++)
#pragma unroll
                for (int j = 0; j < 4; j++)
                    acc[i][j] = fmaf(a[i], bv[j], acc[i][j]);
        }
        __syncthreads();
    }
#pragma unroll
    for (int i = 0; i < 8; i++) {
        int m = m0 + ty*8 + i;
        *(float4*)(g_projm + ((long long)zb * LL + m) * 48 + txx*4) =
            make_float4(acc[i][0], acc[i][1], acc[i][2], acc[i][3]);
    }
}

// ------- layernorm over c (rows contiguous), emits xn hi/lo -------------------
__global__ void __launch_bounds__(256) ln_k(const float* __restrict__ lng,
                                            const float* __restrict__ lnb)
{
    int w = threadIdx.x >> 5, lane = threadIdx.x & 31;
    int tok = blockIdx.x * 8 + w;
    const float* xp = g_xred + (long long)tok * CC;
    float4 v0 = *(const float4*)(xp + lane*4);
    float4 v1 = *(const float4*)(xp + 128 + lane*4);
    float s = v0.x+v0.y+v0.z+v0.w + v1.x+v1.y+v1.z+v1.w;
    float ss = v0.x*v0.x+v0.y*v0.y+v0.z*v0.z+v0.w*v0.w
             + v1.x*v1.x+v1.y*v1.y+v1.z*v1.z+v1.w*v1.w;
#pragma unroll
    for (int o = 16; o; o >>= 1) {
        s  += __shfl_xor_sync(0xffffffffu, s, o);
        ss += __shfl_xor_sync(0xffffffffu, ss, o);
    }
    float mu = s * (1.f/CC);
    float rstd = rsqrtf(ss * (1.f/CC) - mu*mu + 1e-5f);
    float4 g0 = *(const float4*)(lng + lane*4);
    float4 g1 = *(const float4*)(lng + 128 + lane*4);
    float4 b0 = *(const float4*)(lnb + lane*4);
    float4 b1 = *(const float4*)(lnb + 128 + lane*4);
    float vals[8] = {v0.x,v0.y,v0.z,v0.w, v1.x,v1.y,v1.z,v1.w};
    float gs[8] = {g0.x,g0.y,g0.z,g0.w, g1.x,g1.y,g1.z,g1.w};
    float bs[8] = {b0.x,b0.y,b0.z,b0.w, b1.x,b1.y,b1.z,b1.w};
    bf16 hi[8], lo[8];
#pragma unroll
    for (int i = 0; i < 8; i++) {
        float xn = (vals[i] - mu) * rstd * gs[i] + bs[i];
        split_bf(xn, hi[i], lo[i]);
    }
    long long base = (long long)tok * CC;
    *(uint2*)&g_xnhi[base + lane*4] = *(uint2*)&hi[0];
    *(uint2*)&g_xnhi[base + 128 + lane*4] = *(uint2*)&hi[4];
    *(uint2*)&g_xnlo[base + lane*4] = *(uint2*)&lo[0];
    *(uint2*)&g_xnlo[base + 128 + lane*4] = *(uint2*)&lo[4];
}

// -------- causal depthwise conv1d + silu (scan order) -------------------------
#define CCT 64
__global__ void __launch_bounds__(512) conv1d_k(const float* __restrict__ cw,
                                                const float* __restrict__ cb)
{
    __shared__ int sl[CCT + 3];
    int d = threadIdx.x;
    int t0 = blockIdx.x * CCT;
    int b = blockIdx.y;
    int dir = blockIdx.z;
    if (d < CCT + 3) {
        int tt = t0 - 3 + d;
        sl[d] = (tt >= 0) ? g_map[dir * LL + tt] : 0;
    }
    __syncthreads();
    float w0 = cw[d*4+0], w1 = cw[d*4+1], w2 = cw[d*4+2], w3 = cw[d*4+3];
    float bias = cb[d];
    const float* xzb = g_xz + (long long)b * LL * 1024 + d;
    float x0 = 0.f, x1 = 0.f, x2 = 0.f;
    if (t0 > 0) {
        x0 = xzb[(long long)sl[0] * 1024];
        x1 = xzb[(long long)sl[1] * 1024];
        x2 = xzb[(long long)sl[2] * 1024];
    }
    float xn = xzb[(long long)sl[3] * 1024];
    float* yo = &g_xm[(((long long)dir * BB + b) * LL + t0) * DI + d];
    for (int i = 0; i < CCT; i++) {
        float xnn = (i + 1 < CCT) ? xzb[(long long)sl[i + 4] * 1024] : 0.f;
        float s = bias + w0*x0 + w1*x1 + w2*x2 + w3*xn;
        yo[(long long)i * DI] = silu_f(s);
        x0 = x1; x1 = x2; x2 = xn; xn = xnn;
    }
}

// ---------- dt = softplus(proj[:,:16] @ dt_w.T + dt_b) ------------------------
#define DTT 16
__global__ void __launch_bounds__(512) dt_k(const float* __restrict__ dtbias)
{
    __shared__ float pr[DTT][16];
    int d = threadIdx.x;
    int t0 = blockIdx.x * DTT;
    int b = blockIdx.y, dir = blockIdx.z;
    long long row0 = ((long long)dir * BB + b) * LL + t0;
    if (d < DTT * 16) {
        int ti = d >> 4, r = d & 15;
        pr[ti][r] = g_projm[(row0 + ti) * 48 + r];
    }
    float wreg[16];
#pragma unroll
    for (int r = 0; r < 16; r++) wreg[r] = g_dtwT[r * DI + d];
    float bias = dtbias[d];
    __syncthreads();
    float* out = &g_dtb[row0 * DI + d];
#pragma unroll 4
    for (int t = 0; t < DTT; t++) {
        float acc = bias;
#pragma unroll
        for (int r = 0; r < 16; r++) acc = fmaf(pr[t][r], wreg[r], acc);
        float dt = (acc > 15.f) ? acc : log1pf(expf(acc));
        out[(long long)t * DI] = dt;
    }
}

// -------- selective scan: warp = 4 channels x 8 lanes, 2 states/lane ----------
// ex2.approx (single MUFU); ln2 folded into A.
__global__ void __launch_bounds__(128) scan_k(const float* __restrict__ A_log,
                                              const float* __restrict__ Dp)
{
    const float L2E = 1.4426950408889634f;
    int tid = threadIdx.x;
    int lane = tid & 31;
    int gwarp = blockIdx.x * 4 + (tid >> 5);          // 0..1023
    int dir = gwarp >> 8;
    int b = (gwarp >> 7) & 1;
    int d = ((gwarp & 127) << 2) | (lane >> 3);       // 4 channels per warp
    int s = lane & 7;                                 // states s and s+8

    float Av0 = -expf(A_log[d * 16 + s]) * L2E;
    float Av1 = -expf(A_log[d * 16 + s + 8]) * L2E;
    float Dv = Dp[d];
    long long dbase = ((long long)dir * BB + b) * LL;
    const float* pdt = g_dtb + dbase * DI + d;
    const float* pxm = g_xm + dbase * DI + d;
    const float2* pbc0 = reinterpret_cast<const float2*>(g_projm) + dbase * 24 + 8 + s;
    const float2* pbc1 = pbc0 + 8;
    bf16* py = g_y + dbase * DI + d;

    const int PF = 8;
    float f_dt[PF], f_x[PF];
    float2 f_b0[PF], f_b1[PF];
#pragma unroll
    for (int i = 0; i < PF; i++) {
        f_dt[i] = pdt[i * DI];
        f_x[i]  = pxm[i * DI];
        f_b0[i] = pbc0[i * 24];
        f_b1[i] = pbc1[i * 24];
    }
    const float* qdt = pdt + PF * DI;
    const float* qxm = pxm + PF * DI;
    const float2* qb0 = pbc0 + PF * 24;
    const float2* qb1 = pbc1 + PF * 24;

    float h0 = 0.f, h1 = 0.f;
    for (int t0 = 0; t0 < LL; t0 += PF) {
        bool pf = (t0 + PF < LL);
#pragma unroll
        for (int i = 0; i < PF; i++) {
            float dtv = f_dt[i], xv = f_x[i];
            float B0 = f_b0[i].x, C0 = f_b0[i].y;
            float B1 = f_b1[i].x, C1 = f_b1[i].y;
            if (pf) {
                f_dt[i] = qdt[i * DI];
                f_x[i]  = qxm[i * DI];
                f_b0[i] = qb0[i * 24];
                f_b1[i] = qb1[i * 24];
            }
            float dtx = dtv * xv;
            h0 = fmaf(ex2f(dtv * Av0), h0, dtx * B0);
            h1 = fmaf(ex2f(dtv * Av1), h1, dtx * B1);
            float part = fmaf(h0, C0, h1 * C1);
            part += __shfl_xor_sync(0xffffffffu, part, 1);
            part += __shfl_xor_sync(0xffffffffu, part, 2);
            part += __shfl_xor_sync(0xffffffffu, part, 4);
            if (s == 0) py[i * DI] = __float2bfloat16(fmaf(Dv, xv, part));
        }
        qdt += PF * DI; qxm += PF * DI; qb0 += PF * 24; qb1 += PF * 24; py += PF * DI;
    }
}

// ----- gather 4 dirs to natural order, silu(z) gate, emit ysum hi/lo ----------
__global__ void ysum_k()
{
    long long i = (long long)blockIdx.x * blockDim.x + threadIdx.x;
    if (i >= (long long)BL * DI) return;
    int d = (int)(i & (DI - 1));
    int l = (int)((i / DI) % LL);
    int b = (int)(i / ((long long)LL * DI));
    int t2 = (l % WW) * HH + l / WW;
    const long long st = (long long)BB * LL * DI;
    long long bb = (long long)b * LL * DI;
    float y = __bfloat162float(g_y[bb + (long long)l * DI + d])
            + __bfloat162float(g_y[st + bb + (long long)(LL - 1 - l) * DI + d])
            + __bfloat162float(g_y[2 * st + bb + (long long)t2 * DI + d])
            + __bfloat162float(g_y[3 * st + bb + (long long)(LL - 1 - t2) * DI + d]);
    float z = g_xz[((long long)b * LL + l) * 1024 + DI + d];
    float v = y * silu_f(z);
    bf16 h, lo;
    split_bf(v, h, lo);
    long long o = ((long long)b * LL + l) * DI + d;
    g_yshi[o] = h; g_yslo[o] = lo;
}

// ------------- depthwise 1x7 + 7x1, smem-tiled token-major --------------------
__global__ void __launch_bounds__(256) dwconv_tile_k(
    const float* __restrict__ wh, const float* __restrict__ wv,
    const float* __restrict__ hg, const float* __restrict__ hb,
    const float* __restrict__ vg, const float* __restrict__ vb)
{
    __shared__ float sm[14*14*32];
    int b = blockIdx.z;
    int c0 = blockIdx.y * 32;
    int tx0 = (blockIdx.x % 6) * 8, ty0 = (blockIdx.x / 6) * 8;
    int tid = threadIdx.x;

    for (int e = tid; e < 14*14*32; e += 256) {
        int c = e & 31;
        int rest = e >> 5;
        int xx = rest % 14, yy = rest / 14;
        int y = ty0 + yy - 3, x = tx0 + xx - 3;
        float v = 0.f;
        if (y >= 0 && y < HH && x >= 0 && x < WW)
            v = g_p[((long long)b * HWW + y * WW + x) * CC + c0 + c];
        sm[e] = v;
    }
    __syncthreads();

    int c = tid & 31, sy = tid >> 5;
    int cc = c0 + c;
    float whr[7], wvr[7];
#pragma unroll
    for (int j = 0; j < 7; j++) { whr[j] = wh[cc*7 + j]; wvr[j] = wv[cc*7 + j]; }
    float hgv = hg[cc] * BNF, hbv = hb[cc];
    float vgv = vg[cc] * BNF, vbv = vb[cc];

#pragma unroll
    for (int sx = 0; sx < 8; sx++) {
        float sh = 0.f, sv = 0.f;
#pragma unroll
        for (int j = 0; j < 7; j++) {
            sh = fmaf(sm[((sy+3)*14 + sx+j)*32 + c], whr[j], sh);
            sv = fmaf(sm[((sy+j)*14 + sx+3)*32 + c], wvr[j], sv);
        }
        float rh = fmaxf(fmaf(sh, hgv, hbv), 0.f);
        float rv = fmaxf(fmaf(sv, vgv, vbv), 0.f);
        bf16 h, lo;
        split_bf(rh + rv, h, lo);
        long long o = ((long long)b * HWW + (ty0+sy) * WW + tx0 + sx) * CC + cc;
        g_hvhi[o] = h; g_hvlo[o] = lo;
    }
}

// ------------------------- SE head (token-major) ------------------------------
__global__ void mean1_k()
{
    int blk = blockIdx.x, b = blockIdx.y, c = threadIdx.x;
    float s = 0.f;
    for (int i = 0; i < 64; i++) {
        long long idx = ((long long)b * HWW + blk * 64 + i) * CC + c;
        s += g_featloc[idx] + g_featglob[idx];
    }
    g_msum[(b * 36 + blk) * CC + c] = s;
}
__global__ void mean2_k()
{
    int b = blockIdx.x, c = threadIdx.x;
    float s = 0.f;
    for (int i = 0; i < 36; i++) s += g_msum[(b * 36 + i) * CC + c];
    g_sv[b * CC + c] = s / (float)HWW;
}

__global__ void fc_k(const float* __restrict__ fc1, const float* __restrict__ fc2)
{
    int b = blockIdx.x;
    __shared__ float ss[CC], tt[16];
    int tid = threadIdx.x;
    ss[tid] = g_sv[b * CC + tid];
    __syncthreads();
    if (tid < 16) {
        float a = 0.f;
        for (int c = 0; c < CC; c++) a += ss[c] * fc1[tid * CC + c];
        tt[tid] = fmaxf(a, 0.f);
    }
    __syncthreads();
    float z0 = 0.f, z1 = 0.f;
#pragma unroll
    for (int m = 0; m < 16; m++) {
        z0 += tt[m] * fc2[tid * 16 + m];
        z1 += tt[m] * fc2[(CC + tid) * 16 + m];
    }
    float mx = fmaxf(z0, z1);
    float e0 = expf(z0 - mx), e1 = expf(z1 - mx);
    float w0 = e0 / (e0 + e1);
    g_wv[b * 2 * CC + tid] = w0;
    g_wv[b * 2 * CC + CC + tid] = 1.f - w0;
}

// ---- final combine + transpose [l][c] -> out[b][c][hw] -----------------------
__global__ void final_trans_k(float* __restrict__ out)
{
    __shared__ float tile[32][33];
    int b = blockIdx.z;
    int l0 = blockIdx.x * 32, c0 = blockIdx.y * 32;
    int tx = threadIdx.x, ty = threadIdx.y;
    float w0 = g_wv[b * 2 * CC + c0 + tx];
    float w1 = g_wv[b * 2 * CC + CC + c0 + tx];
#pragma unroll
    for (int i = 0; i < 4; i++) {
        long long idx = ((long long)b * HWW + l0 + ty + i*8) * CC + c0 + tx;
        tile[ty + i*8][tx] = w0 * g_featloc[idx] + w1 * g_featglob[idx];
    }
    __syncthreads();
#pragma unroll
    for (int i = 0; i < 4; i++)
        out[((long long)b * CC + c0 + ty + i*8) * HWW + l0 + tx] = tile[tx][ty + i*8];
}

// ------------------------- launch ---------------------------------------------
extern "C" void kernel_launch(void* const* d_in, const int* in_sizes, int n_in,
                              void* d_out, int out_size)
{
    const float* x        = (const float*)d_in[0];
    const float* reduce_w = (const float*)d_in[1];
    const float* bn0_g    = (const float*)d_in[2];
    const float* bn0_b    = (const float*)d_in[3];
    const float* proj_w   = (const float*)d_in[4];
    const float* bn1_g    = (const float*)d_in[5];
    const float* bn1_b    = (const float*)d_in[6];
    const float* dwh_w    = (const float*)d_in[7];
    const float* bnh_g    = (const float*)d_in[8];
    const float* bnh_b    = (const float*)d_in[9];
    const float* dwv_w    = (const float*)d_in[10];
    const float* bnv_g    = (const float*)d_in[11];
    const float* bnv_b    = (const float*)d_in[12];
    const float* fus_w    = (const float*)d_in[13];
    const float* fus_b    = (const float*)d_in[14];
    const float* ln_g     = (const float*)d_in[15];
    const float* ln_b     = (const float*)d_in[16];
    const float* in_w     = (const float*)d_in[17];
    const float* conv_w   = (const float*)d_in[18];
    const float* conv_b   = (const float*)d_in[19];
    const float* xproj_w  = (const float*)d_in[20];
    const float* dt_w     = (const float*)d_in[21];
    const float* dt_b     = (const float*)d_in[22];
    const float* A_log    = (const float*)d_in[23];
    const float* Dp       = (const float*)d_in[24];
    const float* out_w    = (const float*)d_in[25];
    const float* fc1_w    = (const float*)d_in[26];
    const float* fc2_w    = (const float*)d_in[27];

    bf16 *xthi, *xtlo, *rwhi, *rwlo, *pwhi, *pwlo, *fwhi, *fwlo, *owhi, *owlo,
         *xrhi, *xrlo, *hvhi, *hvlo, *yshi, *yslo;
    float *xred, *p, *featloc, *featglob;
    cudaGetSymbolAddress((void**)&xthi, g_xthi);  cudaGetSymbolAddress((void**)&xtlo, g_xtlo);
    cudaGetSymbolAddress((void**)&rwhi, g_rwhi);  cudaGetSymbolAddress((void**)&rwlo, g_rwlo);
    cudaGetSymbolAddress((void**)&pwhi, g_pwhi);  cudaGetSymbolAddress((void**)&pwlo, g_pwlo);
    cudaGetSymbolAddress((void**)&fwhi, g_fwhi);  cudaGetSymbolAddress((void**)&fwlo, g_fwlo);
    cudaGetSymbolAddress((void**)&owhi, g_owhi);  cudaGetSymbolAddress((void**)&owlo, g_owlo);
    cudaGetSymbolAddress((void**)&xrhi, g_xrhi);  cudaGetSymbolAddress((void**)&xrlo, g_xrlo);
    cudaGetSymbolAddress((void**)&hvhi, g_hvhi);  cudaGetSymbolAddress((void**)&hvlo, g_hvlo);
    cudaGetSymbolAddress((void**)&yshi, g_yshi);  cudaGetSymbolAddress((void**)&yslo, g_yslo);
    cudaGetSymbolAddress((void**)&xred, g_xred);
    cudaGetSymbolAddress((void**)&p, g_p);
    cudaGetSymbolAddress((void**)&featloc, g_featloc);
    cudaGetSymbolAddress((void**)&featglob, g_featglob);

    // 0) one-time prep
    init_misc_k<<<2560, 256>>>(dt_w, xproj_w, reduce_w, proj_w, fus_w, in_w, out_w);
    // 1) input transpose + split
    trans_in_k<<<dim3(HWW/32, CIN/32, BB), dim3(32, 8)>>>(x);
    // 2) reduce [tensor]
    gemm_t3s<1><<<dim3(4, 72), 128>>>(xthi, xtlo, rwhi, rwlo,
        xred, xrhi, xrlo, CC, CIN, bn0_g, bn0_b, (const float*)0);
    // 3) layernorm -> xn hi/lo
    ln_k<<<BL/8, 256>>>(ln_g, ln_b);
    // 4) in_proj [tensor big]
    gemm_inproj_t3<<<dim3(8, 36), 256>>>();
    // 5) causal conv1d + silu -> scan-ordered xm
    conv1d_k<<<dim3(LL/CCT, BB, 4), 512>>>(conv_w, conv_b);
    // 6) xproj (SIMT)
    gemm_xproj<<<dim3(18, 8), 192>>>();
    // 7) dt
    dt_k<<<dim3(LL/DTT, BB, 4), 512>>>(dt_b);
    // 8) selective scan (4 channels/warp, 2 states/lane, ex2.approx)
    scan_k<<<256, 128>>>(A_log, Dp);
    // 9) gather + gate -> ysum hi/lo
    ysum_k<<<(BL*DI + 255)/256, 256>>>();
    // 10) out_proj [tensor]
    gemm_t3s<4><<<dim3(4, 72), 128>>>(yshi, yslo, owhi, owlo,
        featglob, (bf16*)0, (bf16*)0, CC, DI, (const float*)0, (const float*)0, xred);
    // 11) proj [tensor]
    gemm_t3s<2><<<dim3(4, 72), 128>>>(xrhi, xrlo, pwhi, pwlo,
        p, (bf16*)0, (bf16*)0, CC, CC, bn1_g, bn1_b, (const float*)0);
    // 12) depthwise h+v (smem-tiled)
    dwconv_tile_k<<<dim3(36, 8, BB), 256>>>(dwh_w, dwv_w, bnh_g, bnh_b, bnv_g, bnv_b);
    // 13) fus [tensor]
    gemm_t3s<3><<<dim3(4, 72), 128>>>(hvhi, hvlo, fwhi, fwlo,
        featloc, (bf16*)0, (bf16*)0, CC, CC, (const float*)0, fus_b, (const float*)0);
    // 14-16) SE head + final combine/transpose
    mean1_k<<<dim3(36, BB), 256>>>();
    mean2_k<<<BB, 256>>>();
    fc_k<<<BB, 256>>>(fc1_w, fc2_w);
    final_trans_k<<<dim3(HWW/32, CC/32, BB), dim3(32, 8)>>>((float*)d_out);
}

// round 17
// speedup vs baseline: 1.5565x; 1.0845x over previous
#include <cuda_runtime.h>
#include <cuda_bf16.h>
#include <stdint.h>
#include <math.h>

#define BB  2
#define CIN 512
#define CC  256
#define HH  48
#define WW  48
#define HWW 2304
#define LL  2304
#define DI  512
#define BL  (BB*LL)
#define BNF 0.9999950000374997f

typedef __nv_bfloat16 bf16;

// ------------------------- static scratch (no allocs) -------------------------
__device__ __align__(256) float g_xred[BL*CC];        // token-major
__device__ __align__(256) float g_p[BL*CC];
__device__ __align__(256) float g_featloc[BL*CC];
__device__ __align__(256) float g_featglob[BL*CC];
__device__ __align__(256) float g_xz[BL*2*DI];
__device__ __align__(256) float g_xm[4*BL*DI];
__device__ __align__(256) float g_projm[4*BL*48];
__device__ __align__(256) float g_dtb[4*BL*DI];
__device__ __align__(256) bf16  g_y[4*BL*DI];
// bf16 split activations
__device__ __align__(256) bf16 g_xthi[BL*CIN],  g_xtlo[BL*CIN];
__device__ __align__(256) bf16 g_xrhi[BL*CC],   g_xrlo[BL*CC];
__device__ __align__(256) bf16 g_xnhi[BL*CC],   g_xnlo[BL*CC];
__device__ __align__(256) bf16 g_hvhi[BL*CC],   g_hvlo[BL*CC];
__device__ __align__(256) bf16 g_yshi[BL*DI],   g_yslo[BL*DI];
// bf16 split weights
__device__ __align__(256) bf16 g_rwhi[CC*CIN],  g_rwlo[CC*CIN];
__device__ __align__(256) bf16 g_pwhi[CC*CC],   g_pwlo[CC*CC];
__device__ __align__(256) bf16 g_fwhi[CC*CC],   g_fwlo[CC*CC];
__device__ __align__(256) bf16 g_iwhi[2*DI*CC], g_iwlo[2*DI*CC];
__device__ __align__(256) bf16 g_owhi[CC*DI],   g_owlo[CC*DI];
// misc
__device__ __align__(256) float g_dtwT[16*DI];
__device__ __align__(256) float g_xpw[48*DI];
__device__ __align__(256) int   g_map[4*LL];
__device__ __align__(256) float g_msum[BB*36*CC];
__device__ __align__(256) float g_sv[BB*CC];
__device__ __align__(256) float g_wv[BB*2*CC];

__device__ __forceinline__ int seq_map(int dir, int t) {
    if (dir == 0) return t;
    if (dir == 1) return LL - 1 - t;
    int u = (dir == 2) ? t : (LL - 1 - t);
    int h = u % HH, w = u / HH;
    return h * WW + w;
}
__device__ __forceinline__ float silu_f(float x) { return x / (1.f + __expf(-x)); }
__device__ __forceinline__ float ex2f(float x) {
    float y;
    asm("ex2.approx.f32 %0, %1;" : "=f"(y) : "f"(x));
    return y;
}
__device__ __forceinline__ void split_bf(float v, bf16& h, bf16& l) {
    h = __float2bfloat16(v);
    l = __float2bfloat16(v - __bfloat162float(h));
}

// ------------------ one-time prep ---------------------------------------------
__global__ void init_misc_k(const float* __restrict__ dtw, const float* __restrict__ xpw,
                            const float* __restrict__ rw, const float* __restrict__ pw,
                            const float* __restrict__ fw, const float* __restrict__ iw,
                            const float* __restrict__ ow)
{
    int i = blockIdx.x * 256 + threadIdx.x;
    if (i < 16 * DI) {
        int dd = i >> 4, r = i & 15;
        g_dtwT[r * DI + dd] = dtw[i];
    }
    if (i < 4 * LL) g_map[i] = seq_map(i / LL, i % LL);
    if (i < 48 * DI) {
        int j = i >> 9, k = i & 511;
        int src = (j < 16) ? j
                : (((j - 16) & 1) ? 32 + ((j - 16) >> 1) : 16 + ((j - 16) >> 1));
        g_xpw[i] = xpw[src * DI + k];
    }
    int o = i;
    if (o < CC*CIN) { split_bf(rw[o], g_rwhi[o], g_rwlo[o]); return; }
    o -= CC*CIN;
    if (o < CC*CC)  { split_bf(pw[o], g_pwhi[o], g_pwlo[o]); return; }
    o -= CC*CC;
    if (o < CC*CC)  { split_bf(fw[o], g_fwhi[o], g_fwlo[o]); return; }
    o -= CC*CC;
    if (o < 2*DI*CC){ split_bf(iw[o], g_iwhi[o], g_iwlo[o]); return; }
    o -= 2*DI*CC;
    if (o < CC*DI)  { split_bf(ow[o], g_owhi[o], g_owlo[o]); return; }
}

// ---------- input transpose: x[b][cin][hw] -> xT hi/lo ------------------------
__global__ void trans_in_k(const float* __restrict__ x)
{
    __shared__ float tile[32][33];
    int b = blockIdx.z;
    int l0 = blockIdx.x * 32, c0 = blockIdx.y * 32;
    int tx = threadIdx.x, ty = threadIdx.y;      // (32,8)
#pragma unroll
    for (int i = 0; i < 4; i++)
        tile[ty + i*8][tx] = x[((long long)b*CIN + c0 + ty + i*8) * HWW + l0 + tx];
    __syncthreads();
#pragma unroll
    for (int i = 0; i < 4; i++) {
        long long o = ((long long)b*HWW + l0 + ty + i*8) * CIN + c0 + tx;
        bf16 h, l;
        split_bf(tile[tx][ty + i*8], h, l);
        g_xthi[o] = h; g_xtlo[o] = l;
    }
}

// ======================= mma primitive ========================================
#define ASTR 40
__device__ __forceinline__ void mma16816(float* d, uint32_t a0, uint32_t a1,
                                         uint32_t a2, uint32_t a3,
                                         uint32_t b0, uint32_t b1)
{
    asm volatile(
        "mma.sync.aligned.m16n8k16.row.col.f32.bf16.bf16.f32 "
        "{%0,%1,%2,%3}, {%4,%5,%6,%7}, {%8,%9}, {%0,%1,%2,%3};\n"
        : "+f"(d[0]), "+f"(d[1]), "+f"(d[2]), "+f"(d[3])
        : "r"(a0), "r"(a1), "r"(a2), "r"(a3), "r"(b0), "r"(b1));
}

// ---------------- big 128x128 tensor GEMM (in_proj) ---------------------------
__global__ void __launch_bounds__(256) gemm_inproj_t3()
{
    __shared__ bf16 As[128 * ASTR];
    __shared__ bf16 Bs[128 * ASTR];
    const int K = CC;
    const int N = 2 * DI;
    int tid = threadIdx.x;
    int warp = tid >> 5, lane = tid & 31;
    int gID = lane >> 2, tig = lane & 3;
    int wm = (warp >> 2) * 64, wn = (warp & 3) * 32;
    int m0 = blockIdx.y * 128, n0 = blockIdx.x * 128;

    int u0 = tid, u1 = tid + 256;
    int ar0 = u0 >> 2, ac0 = (u0 & 3) * 8;
    int ar1 = u1 >> 2, ac1 = (u1 & 3) * 8;

    uint4 ra[2], rb[2];
    ra[0] = *(const uint4*)(g_xnhi + (long long)(m0 + ar0) * K + ac0);
    ra[1] = *(const uint4*)(g_xnhi + (long long)(m0 + ar1) * K + ac1);
    rb[0] = *(const uint4*)(g_iwhi + (long long)(n0 + ar0) * K + ac0);
    rb[1] = *(const uint4*)(g_iwhi + (long long)(n0 + ar1) * K + ac1);

    float acc[4][4][4] = {};
    const int G = 24;

    for (int g = 0; g < G; g++) {
        *(uint4*)&As[ar0 * ASTR + ac0] = ra[0];
        *(uint4*)&As[ar1 * ASTR + ac1] = ra[1];
        *(uint4*)&Bs[ar0 * ASTR + ac0] = rb[0];
        *(uint4*)&Bs[ar1 * ASTR + ac1] = rb[1];
        __syncthreads();
        int gn = g + 1;
        if (gn < G) {
            int pass = gn >> 3;
            int kk = (gn & 7) * 32;
            const bf16* Ag = (pass == 1) ? g_xnlo : g_xnhi;
            const bf16* Bg = (pass == 2) ? g_iwlo : g_iwhi;
            ra[0] = *(const uint4*)(Ag + (long long)(m0 + ar0) * K + kk + ac0);
            ra[1] = *(const uint4*)(Ag + (long long)(m0 + ar1) * K + kk + ac1);
            rb[0] = *(const uint4*)(Bg + (long long)(n0 + ar0) * K + kk + ac0);
            rb[1] = *(const uint4*)(Bg + (long long)(n0 + ar1) * K + kk + ac1);
        }
#pragma unroll
        for (int ks = 0; ks < 32; ks += 16) {
            uint32_t af[4][4], bfr[4][2];
#pragma unroll
            for (int mi = 0; mi < 4; mi++) {
                int r = wm + mi*16 + gID;
                af[mi][0] = *(const uint32_t*)&As[r * ASTR + ks + 2*tig];
                af[mi][1] = *(const uint32_t*)&As[(r+8) * ASTR + ks + 2*tig];
                af[mi][2] = *(const uint32_t*)&As[r * ASTR + ks + 2*tig + 8];
                af[mi][3] = *(const uint32_t*)&As[(r+8) * ASTR + ks + 2*tig + 8];
            }
#pragma unroll
            for (int nj = 0; nj < 4; nj++) {
                int r = wn + nj*8 + gID;
                bfr[nj][0] = *(const uint32_t*)&Bs[r * ASTR + ks + 2*tig];
                bfr[nj][1] = *(const uint32_t*)&Bs[r * ASTR + ks + 2*tig + 8];
            }
#pragma unroll
            for (int mi = 0; mi < 4; mi++)
#pragma unroll
                for (int nj = 0; nj < 4; nj++)
                    mma16816(acc[mi][nj], af[mi][0], af[mi][1], af[mi][2], af[mi][3],
                             bfr[nj][0], bfr[nj][1]);
        }
        __syncthreads();
    }

#pragma unroll
    for (int mi = 0; mi < 4; mi++)
#pragma unroll
    for (int nj = 0; nj < 4; nj++) {
        int m = m0 + wm + mi*16 + gID;
        int n = n0 + wn + nj*8 + 2*tig;
        float* a = acc[mi][nj];
#pragma unroll
        for (int half = 0; half < 2; half++) {
            int mm = m + half * 8;
            *(float2*)&g_xz[(long long)mm * N + n] = make_float2(a[half*2], a[half*2+1]);
        }
    }
}

// ---------------- small 64x64 tensor GEMM (4 warps, warp 32x32) ---------------
template<int MODE>
__global__ void __launch_bounds__(128) gemm_t3s(
    const bf16* __restrict__ Ahi, const bf16* __restrict__ Alo,
    const bf16* __restrict__ Bhi, const bf16* __restrict__ Blo,
    float* __restrict__ outf, bf16* __restrict__ ohi, bf16* __restrict__ olo,
    int N, int K,
    const float* __restrict__ sc, const float* __restrict__ bi,
    const float* __restrict__ extra)
{
    __shared__ bf16 As[64 * ASTR];
    __shared__ bf16 Bs[64 * ASTR];
    int tid = threadIdx.x;
    int warp = tid >> 5, lane = tid & 31;
    int gID = lane >> 2, tig = lane & 3;
    int wm = (warp >> 1) * 32, wn = (warp & 1) * 32;
    int m0 = blockIdx.y * 64, n0 = blockIdx.x * 64;

    int ar = tid >> 2;
    int ac = (tid & 3) * 8;

    int K32 = K >> 5;
    int G = 3 * K32;

    uint4 ra[2], rb[2];
    ra[0] = *(const uint4*)(Ahi + (long long)(m0 + ar) * K + ac);
    ra[1] = *(const uint4*)(Ahi + (long long)(m0 + ar + 32) * K + ac);
    rb[0] = *(const uint4*)(Bhi + (long long)(n0 + ar) * K + ac);
    rb[1] = *(const uint4*)(Bhi + (long long)(n0 + ar + 32) * K + ac);

    float acc[2][4][4] = {};

    for (int g = 0; g < G; g++) {
        *(uint4*)&As[ar * ASTR + ac] = ra[0];
        *(uint4*)&As[(ar + 32) * ASTR + ac] = ra[1];
        *(uint4*)&Bs[ar * ASTR + ac] = rb[0];
        *(uint4*)&Bs[(ar + 32) * ASTR + ac] = rb[1];
        __syncthreads();
        int gn = g + 1;
        if (gn < G) {
            int pass = gn / K32;
            int kk = (gn - pass * K32) * 32;
            const bf16* Ag = (pass == 1) ? Alo : Ahi;
            const bf16* Bg = (pass == 2) ? Blo : Bhi;
            ra[0] = *(const uint4*)(Ag + (long long)(m0 + ar) * K + kk + ac);
            ra[1] = *(const uint4*)(Ag + (long long)(m0 + ar + 32) * K + kk + ac);
            rb[0] = *(const uint4*)(Bg + (long long)(n0 + ar) * K + kk + ac);
            rb[1] = *(const uint4*)(Bg + (long long)(n0 + ar + 32) * K + kk + ac);
        }
#pragma unroll
        for (int ks = 0; ks < 32; ks += 16) {
            uint32_t af[2][4], bfr[4][2];
#pragma unroll
            for (int mi = 0; mi < 2; mi++) {
                int r = wm + mi*16 + gID;
                af[mi][0] = *(const uint32_t*)&As[r * ASTR + ks + 2*tig];
                af[mi][1] = *(const uint32_t*)&As[(r+8) * ASTR + ks + 2*tig];
                af[mi][2] = *(const uint32_t*)&As[r * ASTR + ks + 2*tig + 8];
                af[mi][3] = *(const uint32_t*)&As[(r+8) * ASTR + ks + 2*tig + 8];
            }
#pragma unroll
            for (int nj = 0; nj < 4; nj++) {
                int r = wn + nj*8 + gID;
                bfr[nj][0] = *(const uint32_t*)&Bs[r * ASTR + ks + 2*tig];
                bfr[nj][1] = *(const uint32_t*)&Bs[r * ASTR + ks + 2*tig + 8];
            }
#pragma unroll
            for (int mi = 0; mi < 2; mi++)
#pragma unroll
                for (int nj = 0; nj < 4; nj++)
                    mma16816(acc[mi][nj], af[mi][0], af[mi][1], af[mi][2], af[mi][3],
                             bfr[nj][0], bfr[nj][1]);
        }
        __syncthreads();
    }

#pragma unroll
    for (int mi = 0; mi < 2; mi++)
#pragma unroll
    for (int nj = 0; nj < 4; nj++) {
        int m = m0 + wm + mi*16 + gID;
        int n = n0 + wn + nj*8 + 2*tig;
        float* a = acc[mi][nj];
#pragma unroll
        for (int half = 0; half < 2; half++) {
            int mm = m + half * 8;
            float v0 = a[half*2 + 0], v1 = a[half*2 + 1];
            if (MODE == 1 || MODE == 2) {
                v0 = fmaxf(fmaf(v0, sc[n] * BNF, bi[n]), 0.f);
                v1 = fmaxf(fmaf(v1, sc[n+1] * BNF, bi[n+1]), 0.f);
            } else if (MODE == 3) {
                v0 += bi[n]; v1 += bi[n+1];
            } else if (MODE == 4) {
                const float2 e = *(const float2*)&extra[(long long)mm * N + n];
                v0 = fmaf(v0, 0.25f, e.x);
                v1 = fmaf(v1, 0.25f, e.y);
            }
            long long o = (long long)mm * N + n;
            *(float2*)&outf[o] = make_float2(v0, v1);
            if (MODE == 1) {
                bf16 h0, l0b, h1, l1b;
                split_bf(v0, h0, l0b);
                split_bf(v1, h1, l1b);
                __nv_bfloat162 hh; hh.x = h0; hh.y = h1;
                __nv_bfloat162 ll; ll.x = l0b; ll.y = l1b;
                *(__nv_bfloat162*)&ohi[o] = hh;
                *(__nv_bfloat162*)&olo[o] = ll;
            }
        }
    }
}

// ---------------- xproj (SIMT): proj = xm @ Wperm.T ---------------------------
__global__ void __launch_bounds__(192) gemm_xproj()
{
    __shared__ float As[16][132];
    __shared__ float Bs[16][52];
    int tid = threadIdx.x;
    int zb = blockIdx.y;
    int m0 = blockIdx.x * 128;
    const float* Ab = g_xm + (long long)zb * LL * DI;
    const float* aptr = Ab + (long long)(m0 + tid) * DI;
    int bn = tid >> 2, bk = (tid & 3) * 4;
    const float* bptr = g_xpw + bn * DI + bk;
    int ty = tid / 12, txx = tid % 12;

    float4 pa[4], pbv;
    if (tid < 128) {
#pragma unroll
        for (int j = 0; j < 4; j++) pa[j] = ((const float4*)aptr)[j];
    }
    pbv = *(const float4*)bptr;

    float acc[8][4] = {};
    for (int k0 = 0; k0 < DI; k0 += 16) {
        if (tid < 128) {
#pragma unroll
            for (int j = 0; j < 4; j++) {
                As[j*4+0][tid] = pa[j].x;
                As[j*4+1][tid] = pa[j].y;
                As[j*4+2][tid] = pa[j].z;
                As[j*4+3][tid] = pa[j].w;
            }
        }
        Bs[bk+0][bn] = pbv.x; Bs[bk+1][bn] = pbv.y;
        Bs[bk+2][bn] = pbv.z; Bs[bk+3][bn] = pbv.w;
        __syncthreads();
        if (k0 + 16 < DI) {
            if (tid < 128) {
                const float* an = aptr + k0 + 16;
#pragma unroll
                for (int j = 0; j < 4; j++) pa[j] = ((const float4*)an)[j];
            }
            pbv = *(const float4*)(bptr + k0 + 16);
        }
#pragma unroll
        for (int k = 0; k < 16; k++) {
            float4 a0 = *(const float4*)&As[k][ty*8];
            float4 a1 = *(const float4*)&As[k][ty*8+4];
            float4 b4 = *(const float4*)&Bs[k][txx*4];
            float a[8] = {a0.x,a0.y,a0.z,a0.w,a1.x,a1.y,a1.z,a1.w};
            float bv[4] = {b4.x,b4.y,b4.z,b4.w};
#pragma unroll
            for (int i = 0; i < 8; i++)
#pragma unroll
                for (int j = 0; j < 4; j++)
                    acc[i][j] = fmaf(a[i], bv[j], acc[i][j]);
        }
        __syncthreads();
    }
#pragma unroll
    for (int i = 0; i < 8; i++) {
        int m = m0 + ty*8 + i;
        *(float4*)(g_projm + ((long long)zb * LL + m) * 48 + txx*4) =
            make_float4(acc[i][0], acc[i][1], acc[i][2], acc[i][3]);
    }
}

// ------- layernorm over c (rows contiguous), emits xn hi/lo -------------------
__global__ void __launch_bounds__(256) ln_k(const float* __restrict__ lng,
                                            const float* __restrict__ lnb)
{
    int w = threadIdx.x >> 5, lane = threadIdx.x & 31;
    int tok = blockIdx.x * 8 + w;
    const float* xp = g_xred + (long long)tok * CC;
    float4 v0 = *(const float4*)(xp + lane*4);
    float4 v1 = *(const float4*)(xp + 128 + lane*4);
    float s = v0.x+v0.y+v0.z+v0.w + v1.x+v1.y+v1.z+v1.w;
    float ss = v0.x*v0.x+v0.y*v0.y+v0.z*v0.z+v0.w*v0.w
             + v1.x*v1.x+v1.y*v1.y+v1.z*v1.z+v1.w*v1.w;
#pragma unroll
    for (int o = 16; o; o >>= 1) {
        s  += __shfl_xor_sync(0xffffffffu, s, o);
        ss += __shfl_xor_sync(0xffffffffu, ss, o);
    }
    float mu = s * (1.f/CC);
    float rstd = rsqrtf(ss * (1.f/CC) - mu*mu + 1e-5f);
    float4 g0 = *(const float4*)(lng + lane*4);
    float4 g1 = *(const float4*)(lng + 128 + lane*4);
    float4 b0 = *(const float4*)(lnb + lane*4);
    float4 b1 = *(const float4*)(lnb + 128 + lane*4);
    float vals[8] = {v0.x,v0.y,v0.z,v0.w, v1.x,v1.y,v1.z,v1.w};
    float gs[8] = {g0.x,g0.y,g0.z,g0.w, g1.x,g1.y,g1.z,g1.w};
    float bs[8] = {b0.x,b0.y,b0.z,b0.w, b1.x,b1.y,b1.z,b1.w};
    bf16 hi[8], lo[8];
#pragma unroll
    for (int i = 0; i < 8; i++) {
        float xn = (vals[i] - mu) * rstd * gs[i] + bs[i];
        split_bf(xn, hi[i], lo[i]);
    }
    long long base = (long long)tok * CC;
    *(uint2*)&g_xnhi[base + lane*4] = *(uint2*)&hi[0];
    *(uint2*)&g_xnhi[base + 128 + lane*4] = *(uint2*)&hi[4];
    *(uint2*)&g_xnlo[base + lane*4] = *(uint2*)&lo[0];
    *(uint2*)&g_xnlo[base + 128 + lane*4] = *(uint2*)&lo[4];
}

// -------- causal depthwise conv1d + silu (scan order) -------------------------
#define CCT 64
__global__ void __launch_bounds__(512) conv1d_k(const float* __restrict__ cw,
                                                const float* __restrict__ cb)
{
    __shared__ int sl[CCT + 3];
    int d = threadIdx.x;
    int t0 = blockIdx.x * CCT;
    int b = blockIdx.y;
    int dir = blockIdx.z;
    if (d < CCT + 3) {
        int tt = t0 - 3 + d;
        sl[d] = (tt >= 0) ? g_map[dir * LL + tt] : 0;
    }
    __syncthreads();
    float w0 = cw[d*4+0], w1 = cw[d*4+1], w2 = cw[d*4+2], w3 = cw[d*4+3];
    float bias = cb[d];
    const float* xzb = g_xz + (long long)b * LL * 1024 + d;
    float x0 = 0.f, x1 = 0.f, x2 = 0.f;
    if (t0 > 0) {
        x0 = xzb[(long long)sl[0] * 1024];
        x1 = xzb[(long long)sl[1] * 1024];
        x2 = xzb[(long long)sl[2] * 1024];
    }
    float xn = xzb[(long long)sl[3] * 1024];
    float* yo = &g_xm[(((long long)dir * BB + b) * LL + t0) * DI + d];
    for (int i = 0; i < CCT; i++) {
        float xnn = (i + 1 < CCT) ? xzb[(long long)sl[i + 4] * 1024] : 0.f;
        float s = bias + w0*x0 + w1*x1 + w2*x2 + w3*xn;
        yo[(long long)i * DI] = silu_f(s);
        x0 = x1; x1 = x2; x2 = xn; xn = xnn;
    }
}

// ---------- dt = softplus(proj[:,:16] @ dt_w.T + dt_b) ------------------------
#define DTT 16
__global__ void __launch_bounds__(512) dt_k(const float* __restrict__ dtbias)
{
    __shared__ float pr[DTT][16];
    int d = threadIdx.x;
    int t0 = blockIdx.x * DTT;
    int b = blockIdx.y, dir = blockIdx.z;
    long long row0 = ((long long)dir * BB + b) * LL + t0;
    if (d < DTT * 16) {
        int ti = d >> 4, r = d & 15;
        pr[ti][r] = g_projm[(row0 + ti) * 48 + r];
    }
    float wreg[16];
#pragma unroll
    for (int r = 0; r < 16; r++) wreg[r] = g_dtwT[r * DI + d];
    float bias = dtbias[d];
    __syncthreads();
    float* out = &g_dtb[row0 * DI + d];
#pragma unroll 4
    for (int t = 0; t < DTT; t++) {
        float acc = bias;
#pragma unroll
        for (int r = 0; r < 16; r++) acc = fmaf(pr[t][r], wreg[r], acc);
        float dt = (acc > 15.f) ? acc : log1pf(expf(acc));
        out[(long long)t * DI] = dt;
    }
}

// -------- selective scan: 4 ch x 8 lanes, 2 states/lane, phased shfl ILP ------
__global__ void __launch_bounds__(128) scan_k(const float* __restrict__ A_log,
                                              const float* __restrict__ Dp)
{
    const float L2E = 1.4426950408889634f;
    int tid = threadIdx.x;
    int lane = tid & 31;
    int gwarp = blockIdx.x * 4 + (tid >> 5);          // 0..1023
    int dir = gwarp >> 8;
    int b = (gwarp >> 7) & 1;
    int d = ((gwarp & 127) << 2) | (lane >> 3);       // 4 channels per warp
    int s = lane & 7;                                 // states s and s+8

    float Av0 = -expf(A_log[d * 16 + s]) * L2E;
    float Av1 = -expf(A_log[d * 16 + s + 8]) * L2E;
    float Dv = Dp[d];
    long long dbase = ((long long)dir * BB + b) * LL;
    const float* pdt = g_dtb + dbase * DI + d;
    const float* pxm = g_xm + dbase * DI + d;
    const float2* pbc0 = reinterpret_cast<const float2*>(g_projm) + dbase * 24 + 8 + s;
    const float2* pbc1 = pbc0 + 8;
    bf16* py = g_y + dbase * DI + d;

    const int PF = 8;
    float f_dt[PF], f_x[PF];
    float2 f_b0[PF], f_b1[PF];
#pragma unroll
    for (int i = 0; i < PF; i++) {
        f_dt[i] = pdt[i * DI];
        f_x[i]  = pxm[i * DI];
        f_b0[i] = pbc0[i * 24];
        f_b1[i] = pbc1[i * 24];
    }
    const float* qdt = pdt + PF * DI;
    const float* qxm = pxm + PF * DI;
    const float2* qb0 = pbc0 + PF * 24;
    const float2* qb1 = pbc1 + PF * 24;

    float h0 = 0.f, h1 = 0.f;
    for (int t0 = 0; t0 < LL; t0 += PF) {
        bool pf = (t0 + PF < LL);
        float part[PF], xs[PF];
        // phase 1: serial h chain, bank per-step partials (+ prefetch)
#pragma unroll
        for (int i = 0; i < PF; i++) {
            float dtv = f_dt[i], xv = f_x[i];
            float B0 = f_b0[i].x, C0 = f_b0[i].y;
            float B1 = f_b1[i].x, C1 = f_b1[i].y;
            if (pf) {
                f_dt[i] = qdt[i * DI];
                f_x[i]  = qxm[i * DI];
                f_b0[i] = qb0[i * 24];
                f_b1[i] = qb1[i * 24];
            }
            float dtx = dtv * xv;
            h0 = fmaf(ex2f(dtv * Av0), h0, dtx * B0);
            h1 = fmaf(ex2f(dtv * Av1), h1, dtx * B1);
            part[i] = fmaf(h0, C0, h1 * C1);
            xs[i] = xv;
        }
        // phase 2: 8 independent 3-level shfl trees (ILP hides shfl latency)
#pragma unroll
        for (int i = 0; i < PF; i++)
            part[i] += __shfl_xor_sync(0xffffffffu, part[i], 1);
#pragma unroll
        for (int i = 0; i < PF; i++)
            part[i] += __shfl_xor_sync(0xffffffffu, part[i], 2);
#pragma unroll
        for (int i = 0; i < PF; i++)
            part[i] += __shfl_xor_sync(0xffffffffu, part[i], 4);
        // phase 3: burst stores
        if (s == 0) {
#pragma unroll
            for (int i = 0; i < PF; i++)
                py[i * DI] = __float2bfloat16(fmaf(Dv, xs[i], part[i]));
        }
        qdt += PF * DI; qxm += PF * DI; qb0 += PF * 24; qb1 += PF * 24; py += PF * DI;
    }
}

// ----- gather 4 dirs to natural order, silu(z) gate, emit ysum hi/lo ----------
__global__ void ysum_k()
{
    long long i = (long long)blockIdx.x * blockDim.x + threadIdx.x;
    if (i >= (long long)BL * DI) return;
    int d = (int)(i & (DI - 1));
    int l = (int)((i / DI) % LL);
    int b = (int)(i / ((long long)LL * DI));
    int t2 = (l % WW) * HH + l / WW;
    const long long st = (long long)BB * LL * DI;
    long long bb = (long long)b * LL * DI;
    float y = __bfloat162float(g_y[bb + (long long)l * DI + d])
            + __bfloat162float(g_y[st + bb + (long long)(LL - 1 - l) * DI + d])
            + __bfloat162float(g_y[2 * st + bb + (long long)t2 * DI + d])
            + __bfloat162float(g_y[3 * st + bb + (long long)(LL - 1 - t2) * DI + d]);
    float z = g_xz[((long long)b * LL + l) * 1024 + DI + d];
    float v = y * silu_f(z);
    bf16 h, lo;
    split_bf(v, h, lo);
    long long o = ((long long)b * LL + l) * DI + d;
    g_yshi[o] = h; g_yslo[o] = lo;
}

// ------------- depthwise 1x7 + 7x1, smem-tiled token-major --------------------
__global__ void __launch_bounds__(256) dwconv_tile_k(
    const float* __restrict__ wh, const float* __restrict__ wv,
    const float* __restrict__ hg, const float* __restrict__ hb,
    const float* __restrict__ vg, const float* __restrict__ vb)
{
    __shared__ float sm[14*14*32];
    int b = blockIdx.z;
    int c0 = blockIdx.y * 32;
    int tx0 = (blockIdx.x % 6) * 8, ty0 = (blockIdx.x / 6) * 8;
    int tid = threadIdx.x;

    for (int e = tid; e < 14*14*32; e += 256) {
        int c = e & 31;
        int rest = e >> 5;
        int xx = rest % 14, yy = rest / 14;
        int y = ty0 + yy - 3, x = tx0 + xx - 3;
        float v = 0.f;
        if (y >= 0 && y < HH && x >= 0 && x < WW)
            v = g_p[((long long)b * HWW + y * WW + x) * CC + c0 + c];
        sm[e] = v;
    }
    __syncthreads();

    int c = tid & 31, sy = tid >> 5;
    int cc = c0 + c;
    float whr[7], wvr[7];
#pragma unroll
    for (int j = 0; j < 7; j++) { whr[j] = wh[cc*7 + j]; wvr[j] = wv[cc*7 + j]; }
    float hgv = hg[cc] * BNF, hbv = hb[cc];
    float vgv = vg[cc] * BNF, vbv = vb[cc];

#pragma unroll
    for (int sx = 0; sx < 8; sx++) {
        float sh = 0.f, sv = 0.f;
#pragma unroll
        for (int j = 0; j < 7; j++) {
            sh = fmaf(sm[((sy+3)*14 + sx+j)*32 + c], whr[j], sh);
            sv = fmaf(sm[((sy+j)*14 + sx+3)*32 + c], wvr[j], sv);
        }
        float rh = fmaxf(fmaf(sh, hgv, hbv), 0.f);
        float rv = fmaxf(fmaf(sv, vgv, vbv), 0.f);
        bf16 h, lo;
        split_bf(rh + rv, h, lo);
        long long o = ((long long)b * HWW + (ty0+sy) * WW + tx0 + sx) * CC + cc;
        g_hvhi[o] = h; g_hvlo[o] = lo;
    }
}

// ------------------------- SE head (token-major) ------------------------------
__global__ void mean1_k()
{
    int blk = blockIdx.x, b = blockIdx.y, c = threadIdx.x;
    float s = 0.f;
    for (int i = 0; i < 64; i++) {
        long long idx = ((long long)b * HWW + blk * 64 + i) * CC + c;
        s += g_featloc[idx] + g_featglob[idx];
    }
    g_msum[(b * 36 + blk) * CC + c] = s;
}
__global__ void mean2_k()
{
    int b = blockIdx.x, c = threadIdx.x;
    float s = 0.f;
    for (int i = 0; i < 36; i++) s += g_msum[(b * 36 + i) * CC + c];
    g_sv[b * CC + c] = s / (float)HWW;
}

__global__ void fc_k(const float* __restrict__ fc1, const float* __restrict__ fc2)
{
    int b = blockIdx.x;
    __shared__ float ss[CC], tt[16];
    int tid = threadIdx.x;
    ss[tid] = g_sv[b * CC + tid];
    __syncthreads();
    if (tid < 16) {
        float a = 0.f;
        for (int c = 0; c < CC; c++) a += ss[c] * fc1[tid * CC + c];
        tt[tid] = fmaxf(a, 0.f);
    }
    __syncthreads();
    float z0 = 0.f, z1 = 0.f;
#pragma unroll
    for (int m = 0; m < 16; m++) {
        z0 += tt[m] * fc2[tid * 16 + m];
        z1 += tt[m] * fc2[(CC + tid) * 16 + m];
    }
    float mx = fmaxf(z0, z1);
    float e0 = expf(z0 - mx), e1 = expf(z1 - mx);
    float w0 = e0 / (e0 + e1);
    g_wv[b * 2 * CC + tid] = w0;
    g_wv[b * 2 * CC + CC + tid] = 1.f - w0;
}

// ---- final combine + transpose [l][c] -> out[b][c][hw] -----------------------
__global__ void final_trans_k(float* __restrict__ out)
{
    __shared__ float tile[32][33];
    int b = blockIdx.z;
    int l0 = blockIdx.x * 32, c0 = blockIdx.y * 32;
    int tx = threadIdx.x, ty = threadIdx.y;
    float w0 = g_wv[b * 2 * CC + c0 + tx];
    float w1 = g_wv[b * 2 * CC + CC + c0 + tx];
#pragma unroll
    for (int i = 0; i < 4; i++) {
        long long idx = ((long long)b * HWW + l0 + ty + i*8) * CC + c0 + tx;
        tile[ty + i*8][tx] = w0 * g_featloc[idx] + w1 * g_featglob[idx];
    }
    __syncthreads();
#pragma unroll
    for (int i = 0; i < 4; i++)
        out[((long long)b * CC + c0 + ty + i*8) * HWW + l0 + tx] = tile[tx][ty + i*8];
}

// ------------------------- launch ---------------------------------------------
extern "C" void kernel_launch(void* const* d_in, const int* in_sizes, int n_in,
                              void* d_out, int out_size)
{
    const float* x        = (const float*)d_in[0];
    const float* reduce_w = (const float*)d_in[1];
    const float* bn0_g    = (const float*)d_in[2];
    const float* bn0_b    = (const float*)d_in[3];
    const float* proj_w   = (const float*)d_in[4];
    const float* bn1_g    = (const float*)d_in[5];
    const float* bn1_b    = (const float*)d_in[6];
    const float* dwh_w    = (const float*)d_in[7];
    const float* bnh_g    = (const float*)d_in[8];
    const float* bnh_b    = (const float*)d_in[9];
    const float* dwv_w    = (const float*)d_in[10];
    const float* bnv_g    = (const float*)d_in[11];
    const float* bnv_b    = (const float*)d_in[12];
    const float* fus_w    = (const float*)d_in[13];
    const float* fus_b    = (const float*)d_in[14];
    const float* ln_g     = (const float*)d_in[15];
    const float* ln_b     = (const float*)d_in[16];
    const float* in_w     = (const float*)d_in[17];
    const float* conv_w   = (const float*)d_in[18];
    const float* conv_b   = (const float*)d_in[19];
    const float* xproj_w  = (const float*)d_in[20];
    const float* dt_w     = (const float*)d_in[21];
    const float* dt_b     = (const float*)d_in[22];
    const float* A_log    = (const float*)d_in[23];
    const float* Dp       = (const float*)d_in[24];
    const float* out_w    = (const float*)d_in[25];
    const float* fc1_w    = (const float*)d_in[26];
    const float* fc2_w    = (const float*)d_in[27];

    bf16 *xthi, *xtlo, *rwhi, *rwlo, *pwhi, *pwlo, *fwhi, *fwlo, *owhi, *owlo,
         *xrhi, *xrlo, *hvhi, *hvlo, *yshi, *yslo;
    float *xred, *p, *featloc, *featglob;
    cudaGetSymbolAddress((void**)&xthi, g_xthi);  cudaGetSymbolAddress((void**)&xtlo, g_xtlo);
    cudaGetSymbolAddress((void**)&rwhi, g_rwhi);  cudaGetSymbolAddress((void**)&rwlo, g_rwlo);
    cudaGetSymbolAddress((void**)&pwhi, g_pwhi);  cudaGetSymbolAddress((void**)&pwlo, g_pwlo);
    cudaGetSymbolAddress((void**)&fwhi, g_fwhi);  cudaGetSymbolAddress((void**)&fwlo, g_fwlo);
    cudaGetSymbolAddress((void**)&owhi, g_owhi);  cudaGetSymbolAddress((void**)&owlo, g_owlo);
    cudaGetSymbolAddress((void**)&xrhi, g_xrhi);  cudaGetSymbolAddress((void**)&xrlo, g_xrlo);
    cudaGetSymbolAddress((void**)&hvhi, g_hvhi);  cudaGetSymbolAddress((void**)&hvlo, g_hvlo);
    cudaGetSymbolAddress((void**)&yshi, g_yshi);  cudaGetSymbolAddress((void**)&yslo, g_yslo);
    cudaGetSymbolAddress((void**)&xred, g_xred);
    cudaGetSymbolAddress((void**)&p, g_p);
    cudaGetSymbolAddress((void**)&featloc, g_featloc);
    cudaGetSymbolAddress((void**)&featglob, g_featglob);

    // 0) one-time prep
    init_misc_k<<<2560, 256>>>(dt_w, xproj_w, reduce_w, proj_w, fus_w, in_w, out_w);
    // 1) input transpose + split
    trans_in_k<<<dim3(HWW/32, CIN/32, BB), dim3(32, 8)>>>(x);
    // 2) reduce [tensor]
    gemm_t3s<1><<<dim3(4, 72), 128>>>(xthi, xtlo, rwhi, rwlo,
        xred, xrhi, xrlo, CC, CIN, bn0_g, bn0_b, (const float*)0);
    // 3) layernorm -> xn hi/lo
    ln_k<<<BL/8, 256>>>(ln_g, ln_b);
    // 4) in_proj [tensor big]
    gemm_inproj_t3<<<dim3(8, 36), 256>>>();
    // 5) causal conv1d + silu -> scan-ordered xm
    conv1d_k<<<dim3(LL/CCT, BB, 4), 512>>>(conv_w, conv_b);
    // 6) xproj (SIMT)
    gemm_xproj<<<dim3(18, 8), 192>>>();
    // 7) dt
    dt_k<<<dim3(LL/DTT, BB, 4), 512>>>(dt_b);
    // 8) selective scan (phased shfl ILP)
    scan_k<<<256, 128>>>(A_log, Dp);
    // 9) gather + gate -> ysum hi/lo
    ysum_k<<<(BL*DI + 255)/256, 256>>>();
    // 10) out_proj [tensor]
    gemm_t3s<4><<<dim3(4, 72), 128>>>(yshi, yslo, owhi, owlo,
        featglob, (bf16*)0, (bf16*)0, CC, DI, (const float*)0, (const float*)0, xred);
    // 11) proj [tensor]
    gemm_t3s<2><<<dim3(4, 72), 128>>>(xrhi, xrlo, pwhi, pwlo,
        p, (bf16*)0, (bf16*)0, CC, CC, bn1_g, bn1_b, (const float*)0);
    // 12) depthwise h+v (smem-tiled)
    dwconv_tile_k<<<dim3(36, 8, BB), 256>>>(dwh_w, dwv_w, bnh_g, bnh_b, bnv_g, bnv_b);
    // 13) fus [tensor]
    gemm_t3s<3><<<dim3(4, 72), 128>>>(hvhi, hvlo, fwhi, fwlo,
        featloc, (bf16*)0, (bf16*)0, CC, CC, (const float*)0, fus_b, (const float*)0);
    // 14-16) SE head + final combine/transpose
    mean1_k<<<dim3(36, BB), 256>>>();
    mean2_k<<<BB, 256>>>();
    fc_k<<<BB, 256>>>(fc1_w, fc2_w);
    final_trans_k<<<dim3(HWW/32, CC/32, BB), dim3(32, 8)>>>((float*)d_out);
}